// round 8
// baseline (speedup 1.0000x reference)
#include <cuda_runtime.h>
#include <cuda_bf16.h>
#include <cstdint>

// Problem constants
#define N_ROWS 32768
#define DDIM   512
#define KCODES 4096

// Coarse tiling (int8 IMMA)
#define MT 128                 // rows per CTA
#define NT 128                 // codes per chunk
#define BKB 128                // K int8 elems per SMEM tile
#define NCHUNKS (KCODES / NT)              // 32
#define KT_PER_CHUNK (DDIM / BKB)          // 4
#define TOTAL_TILES (NCHUNKS * KT_PER_CHUNK)  // 128
#define NSTG 2
#define STAGE_BYTES 32768      // A 16KB + B 16KB

// SMEM layout: 2 stages (64KB) + merge scratch (16KB) + running top-8 (8KB)
#define SM_SCR  65536
#define SM_RUN  (65536 + 16384)
#define SMEM_TOTAL (SM_RUN + 8192)   // 90112

#define NCAND 8

// ---------------- scratch ----------------
__device__ int8_t g_Aq[(size_t)N_ROWS * DDIM];
__device__ int8_t g_Cq[(size_t)KCODES * DDIM];
__device__ float  g_sA2[N_ROWS];     // -2 * rowmax/127  (inputs)
__device__ float  g_sC[KCODES];      //      rowmax/127  (codebook)
__device__ float  g_cnorm[KCODES];   // exact fp32 ||c||^2
__device__ int    g_cand[N_ROWS * NCAND];

// ---------------- PTX helpers ----------------
__device__ __forceinline__ uint32_t smem_to_u32(const void* p) {
    uint32_t a;
    asm("{ .reg .u64 t; cvta.to.shared.u64 t, %1; cvt.u32.u64 %0, t; }" : "=r"(a) : "l"(p));
    return a;
}
__device__ __forceinline__ void cp_async16(uint32_t dst, const void* src) {
    asm volatile("cp.async.cg.shared.global [%0], [%1], 16;" :: "r"(dst), "l"(src) : "memory");
}
#define CP_COMMIT() asm volatile("cp.async.commit_group;" ::: "memory")
#define CP_WAIT(n)  asm volatile("cp.async.wait_group %0;" :: "n"(n) : "memory")

__device__ __forceinline__ void ldsm_x4(uint32_t& r0, uint32_t& r1, uint32_t& r2,
                                        uint32_t& r3, uint32_t addr) {
    asm volatile("ldmatrix.sync.aligned.m8n8.x4.shared.b16 {%0,%1,%2,%3}, [%4];"
                 : "=r"(r0), "=r"(r1), "=r"(r2), "=r"(r3) : "r"(addr));
}
__device__ __forceinline__ void imma16832(int* d, const uint32_t* a,
                                          uint32_t b0, uint32_t b1) {
    asm volatile(
        "mma.sync.aligned.m16n8k32.row.col.s32.s8.s8.s32 "
        "{%0,%1,%2,%3}, {%4,%5,%6,%7}, {%8,%9}, {%0,%1,%2,%3};"
        : "+r"(d[0]), "+r"(d[1]), "+r"(d[2]), "+r"(d[3])
        : "r"(a[0]), "r"(a[1]), "r"(a[2]), "r"(a[3]), "r"(b0), "r"(b1));
}
__device__ __forceinline__ uint32_t sw_off(int row, int chunk) {
    return (uint32_t)(row * 128 + ((chunk ^ (row & 7)) << 4));
}
// monotone float -> u32 (ascending float <-> ascending uint), pack with idx
__device__ __forceinline__ uint64_t packkey(float v, int idx) {
    uint32_t u = __float_as_uint(v);
    u = (u & 0x80000000u) ? ~u : (u | 0x80000000u);
    return ((uint64_t)u << 32) | (uint32_t)idx;
}

// ---------------------------------------------------------------------------
// Quantize inputs per-row: one block (128 thr) per row
// ---------------------------------------------------------------------------
__global__ void quant_inputs_kernel(const float* __restrict__ src) {
    const int n = blockIdx.x;
    float4 v = reinterpret_cast<const float4*>(src + (size_t)n * DDIM)[threadIdx.x];
    float m = fmaxf(fmaxf(fabsf(v.x), fabsf(v.y)), fmaxf(fabsf(v.z), fabsf(v.w)));
#pragma unroll
    for (int o = 16; o > 0; o >>= 1) m = fmaxf(m, __shfl_xor_sync(0xffffffffu, m, o));
    __shared__ float ws[4];
    if ((threadIdx.x & 31) == 0) ws[threadIdx.x >> 5] = m;
    __syncthreads();
    m = fmaxf(fmaxf(ws[0], ws[1]), fmaxf(ws[2], ws[3]));
    m = fmaxf(m, 1e-20f);
    const float inv = 127.0f / m;
    int8_t b[4];
    b[0] = (int8_t)__float2int_rn(v.x * inv);
    b[1] = (int8_t)__float2int_rn(v.y * inv);
    b[2] = (int8_t)__float2int_rn(v.z * inv);
    b[3] = (int8_t)__float2int_rn(v.w * inv);
    reinterpret_cast<uint32_t*>(g_Aq)[n * (DDIM / 4) + threadIdx.x] =
        *reinterpret_cast<uint32_t*>(b);
    if (threadIdx.x == 0) g_sA2[n] = -2.0f * (m / 127.0f);
}

// ---------------------------------------------------------------------------
// Quantize codebook per-row + exact fp32 cnorm: one block (128 thr) per row
// ---------------------------------------------------------------------------
__global__ void quant_codebook_kernel(const float* __restrict__ cb) {
    const int k = blockIdx.x;
    float4 v = reinterpret_cast<const float4*>(cb + (size_t)k * DDIM)[threadIdx.x];
    float m = fmaxf(fmaxf(fabsf(v.x), fabsf(v.y)), fmaxf(fabsf(v.z), fabsf(v.w)));
    float s = v.x * v.x + v.y * v.y + v.z * v.z + v.w * v.w;
#pragma unroll
    for (int o = 16; o > 0; o >>= 1) {
        m = fmaxf(m, __shfl_xor_sync(0xffffffffu, m, o));
        s += __shfl_xor_sync(0xffffffffu, s, o);
    }
    __shared__ float wm_[4], ws[4];
    if ((threadIdx.x & 31) == 0) { wm_[threadIdx.x >> 5] = m; ws[threadIdx.x >> 5] = s; }
    __syncthreads();
    m = fmaxf(fmaxf(wm_[0], wm_[1]), fmaxf(wm_[2], wm_[3]));
    m = fmaxf(m, 1e-20f);
    const float inv = 127.0f / m;
    int8_t b[4];
    b[0] = (int8_t)__float2int_rn(v.x * inv);
    b[1] = (int8_t)__float2int_rn(v.y * inv);
    b[2] = (int8_t)__float2int_rn(v.z * inv);
    b[3] = (int8_t)__float2int_rn(v.w * inv);
    reinterpret_cast<uint32_t*>(g_Cq)[k * (DDIM / 4) + threadIdx.x] =
        *reinterpret_cast<uint32_t*>(b);
    if (threadIdx.x == 0) {
        g_sC[k] = m / 127.0f;
        g_cnorm[k] = ws[0] + ws[1] + ws[2] + ws[3];
    }
}

// ---------------------------------------------------------------------------
// Coarse pass: int8 IMMA GEMM + per-thread top-2 per row-slot,
// merged into per-row smem top-8 every 8 chunks.
// Grid 256 CTAs x 256 threads, 2 CTAs/SM. 8 warps (4m x 2n), warp tile 32x64.
// ---------------------------------------------------------------------------
__device__ __forceinline__ void issue_stage(uint32_t aBase, uint32_t bBase,
                                            int r0, int c0, int ks, int tid) {
#pragma unroll
    for (int i = 0; i < 4; ++i) {
        int idx = tid + i * 256;        // 0..1023
        int row = idx >> 3, ch = idx & 7;
        cp_async16(aBase + sw_off(row, ch),
                   g_Aq + (size_t)(r0 + row) * DDIM + ks + ch * 16);
    }
#pragma unroll
    for (int i = 0; i < 4; ++i) {
        int idx = tid + i * 256;
        int row = idx >> 3, ch = idx & 7;
        cp_async16(bBase + sw_off(row, ch),
                   g_Cq + (size_t)(c0 + row) * DDIM + ks + ch * 16);
    }
    CP_COMMIT();
}

__global__ void __launch_bounds__(256, 2)
vq_coarse_kernel() {
    extern __shared__ char smem[];
    const uint32_t sb = smem_to_u32(smem);
    uint64_t* scr = reinterpret_cast<uint64_t*>(smem + SM_SCR);   // [128][16]
    uint64_t* run = reinterpret_cast<uint64_t*>(smem + SM_RUN);   // [128][8]
    const int tid  = threadIdx.x;
    const int lane = tid & 31;
    const int warp = tid >> 5;
    const int wm = warp >> 1;          // 0..3 (32 rows each)
    const int wn = warp & 1;           // 0..1 (64 codes each)
    const int r0 = blockIdx.x * MT;

    const int sub  = lane >> 3;
    const int lrow = (sub & 1) * 8 + (lane & 7);
    const int lchk = sub >> 1;

    // init running top-8 lists
    for (int i = tid; i < MT * 8; i += 256) run[i] = 0xFFFFFFFFFFFFFFFFull;

    // per-slot input scales (-2 * sA) ; slot = mi*2 + rowhalf
    float sA2[4];
#pragma unroll
    for (int s = 0; s < 4; ++s) {
        const int mi = s >> 1, rh = s & 1;
        sA2[s] = g_sA2[r0 + wm * 32 + mi * 16 + rh * 8 + (lane >> 2)];
    }

    int acc[2][8][4];
#pragma unroll
    for (int mi = 0; mi < 2; ++mi)
#pragma unroll
        for (int n8 = 0; n8 < 8; ++n8)
#pragma unroll
            for (int e = 0; e < 4; ++e) acc[mi][n8][e] = 0;

    float v0[4], v1[4];
    int   i0[4], i1[4];
#pragma unroll
    for (int s = 0; s < 4; ++s) { v0[s] = v1[s] = 3.0e38f; i0[s] = i1[s] = 0x7fffffff; }

    issue_stage(sb, sb + 16384, r0, 0, 0, tid);
    issue_stage(sb + STAGE_BYTES, sb + STAGE_BYTES + 16384, r0, 0, BKB, tid);

#pragma unroll 1
    for (int t = 0; t < TOTAL_TILES; ++t) {
        const int chunk = t >> 2;
        const int kt = t & 3;

        if (t == TOTAL_TILES - 1) { CP_WAIT(0); } else { CP_WAIT(1); }
        __syncthreads();

        const uint32_t aBase = sb + (t & 1) * STAGE_BYTES;
        const uint32_t bBase = aBase + 16384;
#pragma unroll
        for (int kk = 0; kk < 4; ++kk) {
            uint32_t a[2][4];
#pragma unroll
            for (int mi = 0; mi < 2; ++mi)
                ldsm_x4(a[mi][0], a[mi][1], a[mi][2], a[mi][3],
                        aBase + sw_off(wm * 32 + mi * 16 + lrow, kk * 2 + lchk));
            uint32_t bfr[4][4];
#pragma unroll
            for (int ni = 0; ni < 4; ++ni)
                ldsm_x4(bfr[ni][0], bfr[ni][1], bfr[ni][2], bfr[ni][3],
                        bBase + sw_off(wn * 64 + ni * 16 + lrow, kk * 2 + lchk));
#pragma unroll
            for (int mi = 0; mi < 2; ++mi)
#pragma unroll
                for (int n8 = 0; n8 < 8; ++n8)
                    imma16832(acc[mi][n8], a[mi],
                              bfr[n8 >> 1][n8 & 1], bfr[n8 >> 1][(n8 & 1) + 2]);
        }

        if (kt == KT_PER_CHUNK - 1) {
            const int c0 = chunk * NT;
#pragma unroll
            for (int n8 = 0; n8 < 8; ++n8) {
                const int col = c0 + wn * 64 + n8 * 8 + 2 * (lane & 3);
                const float cn0 = __ldg(&g_cnorm[col]);
                const float cn1 = __ldg(&g_cnorm[col + 1]);
                const float sc0 = __ldg(&g_sC[col]);
                const float sc1 = __ldg(&g_sC[col + 1]);
#pragma unroll
                for (int mi = 0; mi < 2; ++mi) {
#pragma unroll
                    for (int e = 0; e < 4; ++e) {
                        const int slot = mi * 2 + (e >> 1);
                        const float cn = (e & 1) ? cn1 : cn0;
                        const float sc = (e & 1) ? sc1 : sc0;
                        const int   cx = col + (e & 1);
                        float d = fmaf(sA2[slot] * sc, (float)acc[mi][n8][e], cn);
                        if (d < v1[slot]) {
                            if (d < v0[slot]) {
                                v1[slot] = v0[slot]; i1[slot] = i0[slot];
                                v0[slot] = d;        i0[slot] = cx;
                            } else { v1[slot] = d; i1[slot] = cx; }
                        }
                        acc[mi][n8][e] = 0;
                    }
                }
            }

            // Every 8 chunks: merge per-thread top-2 into per-row smem top-8
            if ((chunk & 7) == 7) {
                __syncthreads();   // run/scr not in use by others yet
#pragma unroll
                for (int slot = 0; slot < 4; ++slot) {
                    const int mi = slot >> 1, rh = slot & 1;
                    const int row = wm * 32 + mi * 16 + rh * 8 + (lane >> 2);
                    const int col = wn * 8 + (lane & 3) * 2;
                    scr[row * 16 + col]     = packkey(v0[slot], i0[slot]);
                    scr[row * 16 + col + 1] = packkey(v1[slot], i1[slot]);
                    v0[slot] = v1[slot] = 3.0e38f;
                    i0[slot] = i1[slot] = 0x7fffffff;
                }
                __syncthreads();
                if (tid < MT) {
                    uint64_t r[8];
#pragma unroll
                    for (int j = 0; j < 8; ++j) r[j] = run[tid * 8 + j];
#pragma unroll 4
                    for (int e = 0; e < 16; ++e) {
                        uint64_t x = scr[tid * 16 + e];
                        if (x < r[7]) {
                            r[7] = x;
#pragma unroll
                            for (int j = 7; j >= 1; --j)
                                if (r[j] < r[j-1]) { uint64_t f = r[j]; r[j] = r[j-1]; r[j-1] = f; }
                        }
                    }
#pragma unroll
                    for (int j = 0; j < 8; ++j) run[tid * 8 + j] = r[j];
                }
            }
        }

        __syncthreads();  // stage (t&1) free for tile t+2
        if (t + 2 < TOTAL_TILES) {
            const int t2 = t + 2;
            issue_stage(sb + (t2 & 1) * STAGE_BYTES,
                        sb + (t2 & 1) * STAGE_BYTES + 16384,
                        r0, (t2 >> 2) * NT, (t2 & 3) * BKB, tid);
        }
    }

    // write candidates
    if (tid < MT) {
#pragma unroll
        for (int j = 0; j < NCAND; ++j)
            g_cand[(r0 + tid) * NCAND + j] = (int)(run[tid * 8 + j] & 0xFFFFFFFFu);
    }
}

// ---------------------------------------------------------------------------
// Exact refine + gather. One warp per row; 8 candidates, fp32 dots.
// ---------------------------------------------------------------------------
__global__ void __launch_bounds__(256)
refine_kernel(const float* __restrict__ cb, const float* __restrict__ x,
              float* __restrict__ out) {
    const int n = blockIdx.x * 8 + (threadIdx.x >> 5);
    const int lane = threadIdx.x & 31;

    float xr[16];
#pragma unroll
    for (int j = 0; j < 16; ++j) xr[j] = x[(size_t)n * DDIM + j * 32 + lane];

    float bv = 3.0e38f;
    int   bi = 0x7fffffff;
#pragma unroll
    for (int c = 0; c < NCAND; ++c) {
        const int k = g_cand[n * NCAND + c];
        const float* crow = cb + (size_t)k * DDIM;
        float s = 0.f;
#pragma unroll
        for (int j = 0; j < 16; ++j) s = fmaf(xr[j], __ldg(crow + j * 32 + lane), s);
#pragma unroll
        for (int o = 16; o > 0; o >>= 1) s += __shfl_xor_sync(0xffffffffu, s, o);
        float d2 = fmaf(-2.f, s, __ldg(&g_cnorm[k]));
        if (d2 < bv || (d2 == bv && k < bi)) { bv = d2; bi = k; }
    }

    const float* q = cb + (size_t)bi * DDIM;
#pragma unroll
    for (int j = 0; j < 16; ++j) {
        float qv = __ldg(q + j * 32 + lane);
        float xv = xr[j];
        out[(size_t)n * DDIM + j * 32 + lane] = (qv - xv) + xv;
    }
}

// ---------------------------------------------------------------------------
extern "C" void kernel_launch(void* const* d_in, const int* in_sizes, int n_in,
                              void* d_out, int out_size) {
    const float* inputs   = (const float*)d_in[0];
    const float* codebook = (const float*)d_in[1];
    float* out = (float*)d_out;

    cudaFuncSetAttribute(vq_coarse_kernel, cudaFuncAttributeMaxDynamicSharedMemorySize,
                         SMEM_TOTAL);

    quant_inputs_kernel<<<N_ROWS, 128>>>(inputs);
    quant_codebook_kernel<<<KCODES, 128>>>(codebook);
    vq_coarse_kernel<<<N_ROWS / MT, 256, SMEM_TOTAL>>>();
    refine_kernel<<<N_ROWS / 8, 256>>>(codebook, inputs, out);
}

// round 9
// speedup vs baseline: 1.8140x; 1.8140x over previous
#include <cuda_runtime.h>
#include <cuda_bf16.h>
#include <cstdint>

// Problem constants
#define N_ROWS 32768
#define DDIM   512
#define KCODES 4096

// Coarse tiling (bf16 HMMA)
#define MT 128                 // rows per CTA
#define NTC 256                // codes per chunk (CTA tile 128x256)
#define BK 64                  // K bf16 per SMEM tile (128B rows)
#define NCHUNKS (KCODES / NTC)             // 16
#define KT_PER_CHUNK (DDIM / BK)           // 8
#define TOTAL_TILES (NCHUNKS * KT_PER_CHUNK)  // 128
#define NSTG 3
#define STAGE_BYTES 49152      // A 16KB + B 32KB

#define SM_SCR (NSTG * STAGE_BYTES)        // 147456: [128][32] u64 = 32KB
#define SM_RUN (SM_SCR + 32768)            // 180224: [128][8] u64 = 8KB
#define SMEM_TOTAL (SM_RUN + 8192)         // 188416

#define NCAND 8

// ---------------- scratch ----------------
__device__ __nv_bfloat16 g_Ah[(size_t)N_ROWS * DDIM];
__device__ __nv_bfloat16 g_Ch[(size_t)KCODES * DDIM];
__device__ float g_cnorm[KCODES];
__device__ int   g_cand[N_ROWS * NCAND];

// ---------------- PTX helpers ----------------
__device__ __forceinline__ uint32_t smem_to_u32(const void* p) {
    uint32_t a;
    asm("{ .reg .u64 t; cvta.to.shared.u64 t, %1; cvt.u32.u64 %0, t; }" : "=r"(a) : "l"(p));
    return a;
}
__device__ __forceinline__ void cp_async16(uint32_t dst, const void* src) {
    asm volatile("cp.async.cg.shared.global [%0], [%1], 16;" :: "r"(dst), "l"(src) : "memory");
}
#define CP_COMMIT() asm volatile("cp.async.commit_group;" ::: "memory")
#define CP_WAIT(n)  asm volatile("cp.async.wait_group %0;" :: "n"(n) : "memory")

__device__ __forceinline__ void ldsm_x4(uint32_t& r0, uint32_t& r1, uint32_t& r2,
                                        uint32_t& r3, uint32_t addr) {
    asm volatile("ldmatrix.sync.aligned.m8n8.x4.shared.b16 {%0,%1,%2,%3}, [%4];"
                 : "=r"(r0), "=r"(r1), "=r"(r2), "=r"(r3) : "r"(addr));
}
__device__ __forceinline__ void mma16816(float* d, const uint32_t* a,
                                         uint32_t b0, uint32_t b1) {
    asm volatile(
        "mma.sync.aligned.m16n8k16.row.col.f32.bf16.bf16.f32 "
        "{%0,%1,%2,%3}, {%4,%5,%6,%7}, {%8,%9}, {%0,%1,%2,%3};"
        : "+f"(d[0]), "+f"(d[1]), "+f"(d[2]), "+f"(d[3])
        : "r"(a[0]), "r"(a[1]), "r"(a[2]), "r"(a[3]), "r"(b0), "r"(b1));
}
__device__ __forceinline__ uint32_t sw_off(int row, int chunk) {
    return (uint32_t)(row * 128 + ((chunk ^ (row & 7)) << 4));
}
// monotone float->u32 pack with idx (ascending u64 order == ascending (d2, idx))
__device__ __forceinline__ uint64_t packkey(float v, int idx) {
    uint32_t u = __float_as_uint(v);
    u = (u & 0x80000000u) ? ~u : (u | 0x80000000u);
    return ((uint64_t)u << 32) | (uint32_t)idx;
}

// ---------------------------------------------------------------------------
// Precompute: inputs fp32 -> bf16 ; codebook -> bf16 + exact fp32 ||c||^2
// ---------------------------------------------------------------------------
__global__ void split_inputs_kernel(const float* __restrict__ src) {
    int n4 = N_ROWS * DDIM / 4;
    for (int i = blockIdx.x * blockDim.x + threadIdx.x; i < n4; i += gridDim.x * blockDim.x) {
        float4 v = reinterpret_cast<const float4*>(src)[i];
        __nv_bfloat16 h[4] = {__float2bfloat16_rn(v.x), __float2bfloat16_rn(v.y),
                              __float2bfloat16_rn(v.z), __float2bfloat16_rn(v.w)};
        reinterpret_cast<uint2*>(g_Ah)[i] = *reinterpret_cast<uint2*>(h);
    }
}
__global__ void quant_codebook_kernel(const float* __restrict__ cb) {
    int k = blockIdx.x;
    float4 v = reinterpret_cast<const float4*>(cb + (size_t)k * DDIM)[threadIdx.x];
    __nv_bfloat16 h[4] = {__float2bfloat16_rn(v.x), __float2bfloat16_rn(v.y),
                          __float2bfloat16_rn(v.z), __float2bfloat16_rn(v.w)};
    reinterpret_cast<uint2*>(g_Ch)[k * (DDIM / 4) + threadIdx.x] =
        *reinterpret_cast<uint2*>(h);
    float s = v.x * v.x + v.y * v.y + v.z * v.z + v.w * v.w;
#pragma unroll
    for (int o = 16; o > 0; o >>= 1) s += __shfl_xor_sync(0xffffffffu, s, o);
    __shared__ float ws[4];
    if ((threadIdx.x & 31) == 0) ws[threadIdx.x >> 5] = s;
    __syncthreads();
    if (threadIdx.x == 0) g_cnorm[k] = ws[0] + ws[1] + ws[2] + ws[3];
}

// ---------------------------------------------------------------------------
// Coarse pass: bf16 GEMM 128x256 per chunk; warp tile 64x64 (8 warps, 2m x 4n).
// Per chunk: transient per-thread top-2 per row-slot -> smem top-8 merge.
// Grid 256 CTAs x 256 threads, 1 CTA/SM.
// ---------------------------------------------------------------------------
__device__ __forceinline__ void issue_stage(uint32_t aBase, uint32_t bBase,
                                            int r0, int c0, int ks, int tid) {
#pragma unroll
    for (int i = 0; i < 4; ++i) {           // A: 128 rows x 8 chunks
        int idx = tid + i * 256;
        int row = idx >> 3, ch = idx & 7;
        cp_async16(aBase + sw_off(row, ch),
                   g_Ah + (size_t)(r0 + row) * DDIM + ks + ch * 8);
    }
#pragma unroll
    for (int i = 0; i < 8; ++i) {           // B: 256 rows x 8 chunks
        int idx = tid + i * 256;
        int row = idx >> 3, ch = idx & 7;
        cp_async16(bBase + sw_off(row, ch),
                   g_Ch + (size_t)(c0 + row) * DDIM + ks + ch * 8);
    }
    CP_COMMIT();
}

__global__ void __launch_bounds__(256, 1)
vq_coarse_kernel() {
    extern __shared__ char smem[];
    const uint32_t sb = smem_to_u32(smem);
    uint64_t* scr = reinterpret_cast<uint64_t*>(smem + SM_SCR);   // [128][32]
    uint64_t* run = reinterpret_cast<uint64_t*>(smem + SM_RUN);   // [128][8]
    const int tid  = threadIdx.x;
    const int lane = tid & 31;
    const int warp = tid >> 5;
    const int wm = warp >> 2;          // 0..1 (64 rows each)
    const int wn = warp & 3;           // 0..3 (64 codes each)
    const int r0 = blockIdx.x * MT;

    const int sub  = lane >> 3;
    const int lrow = (sub & 1) * 8 + (lane & 7);
    const int lchk = sub >> 1;

    for (int i = tid; i < MT * 8; i += 256) run[i] = 0xFFFFFFFFFFFFFFFFull;

    float acc[4][8][4];                // 64 rows (4 m16) x 64 codes (8 n8)
#pragma unroll
    for (int mi = 0; mi < 4; ++mi)
#pragma unroll
        for (int n8 = 0; n8 < 8; ++n8)
#pragma unroll
            for (int e = 0; e < 4; ++e) acc[mi][n8][e] = 0.f;

    issue_stage(sb, sb + 16384, r0, 0, 0, tid);
    issue_stage(sb + STAGE_BYTES, sb + STAGE_BYTES + 16384, r0, 0, BK, tid);

#pragma unroll 1
    for (int t = 0; t < TOTAL_TILES; ++t) {
        const int chunk = t >> 3;
        const int kt = t & 7;

        if (t == TOTAL_TILES - 1) { CP_WAIT(0); } else { CP_WAIT(1); }
        __syncthreads();

        if (t + 2 < TOTAL_TILES) {
            const int t2 = t + 2;
            const int s2 = t2 % NSTG;
            issue_stage(sb + s2 * STAGE_BYTES, sb + s2 * STAGE_BYTES + 16384,
                        r0, (t2 >> 3) * NTC, (t2 & 7) * BK, tid);
        }

        const uint32_t aBase = sb + (t % NSTG) * STAGE_BYTES;
        const uint32_t bBase = aBase + 16384;
#pragma unroll
        for (int kk = 0; kk < 4; ++kk) {
            uint32_t a[4][4];
#pragma unroll
            for (int mi = 0; mi < 4; ++mi)
                ldsm_x4(a[mi][0], a[mi][1], a[mi][2], a[mi][3],
                        aBase + sw_off(wm * 64 + mi * 16 + lrow, kk * 2 + lchk));
            uint32_t bfr[4][4];
#pragma unroll
            for (int ni = 0; ni < 4; ++ni)
                ldsm_x4(bfr[ni][0], bfr[ni][1], bfr[ni][2], bfr[ni][3],
                        bBase + sw_off(wn * 64 + ni * 16 + lrow, kk * 2 + lchk));
#pragma unroll
            for (int mi = 0; mi < 4; ++mi)
#pragma unroll
                for (int n8 = 0; n8 < 8; ++n8)
                    mma16816(acc[mi][n8], a[mi],
                             bfr[n8 >> 1][n8 & 1], bfr[n8 >> 1][(n8 & 1) + 2]);
        }

        // Chunk epilogue: d2, transient per-slot top-2, smem top-8 merge
        if (kt == KT_PER_CHUNK - 1) {
            const int c0 = chunk * NTC;
            float tv0[8], tv1[8];
            int   ti0[8], ti1[8];
#pragma unroll
            for (int s = 0; s < 8; ++s) { tv0[s] = tv1[s] = 3.0e38f; ti0[s] = ti1[s] = 0; }
#pragma unroll
            for (int n8 = 0; n8 < 8; ++n8) {
                const int col = c0 + wn * 64 + n8 * 8 + 2 * (lane & 3);
                const float cn0 = __ldg(&g_cnorm[col]);
                const float cn1 = __ldg(&g_cnorm[col + 1]);
#pragma unroll
                for (int mi = 0; mi < 4; ++mi) {
#pragma unroll
                    for (int e = 0; e < 4; ++e) {
                        const int slot = mi * 2 + (e >> 1);
                        const float cn = (e & 1) ? cn1 : cn0;
                        const int   cx = col + (e & 1);
                        float d = fmaf(-2.f, acc[mi][n8][e], cn);
                        if (d < tv1[slot]) {
                            if (d < tv0[slot]) {
                                tv1[slot] = tv0[slot]; ti1[slot] = ti0[slot];
                                tv0[slot] = d;         ti0[slot] = cx;
                            } else { tv1[slot] = d; ti1[slot] = cx; }
                        }
                        acc[mi][n8][e] = 0.f;
                    }
                }
            }
            const int contrib = wn * 4 + (lane & 3);   // 0..15
#pragma unroll
            for (int slot = 0; slot < 8; ++slot) {
                const int row = wm * 64 + (slot >> 1) * 16 + (slot & 1) * 8 + (lane >> 2);
                scr[row * 32 + contrib * 2]     = packkey(tv0[slot], ti0[slot]);
                scr[row * 32 + contrib * 2 + 1] = packkey(tv1[slot], ti1[slot]);
            }
            __syncthreads();
            if (tid < MT) {
                uint64_t r[8];
#pragma unroll
                for (int j = 0; j < 8; ++j) r[j] = run[tid * 8 + j];
#pragma unroll 4
                for (int e = 0; e < 32; ++e) {
                    uint64_t x = scr[tid * 32 + e];
                    if (x < r[7]) {
                        r[7] = x;
#pragma unroll
                        for (int j = 7; j >= 1; --j)
                            if (r[j] < r[j-1]) { uint64_t f = r[j]; r[j] = r[j-1]; r[j-1] = f; }
                    }
                }
#pragma unroll
                for (int j = 0; j < 8; ++j) run[tid * 8 + j] = r[j];
            }
            // next tile's leading __syncthreads orders merge-read vs next scr-write
        }
    }

    __syncthreads();
    if (tid < MT) {
#pragma unroll
        for (int j = 0; j < NCAND; ++j)
            g_cand[(r0 + tid) * NCAND + j] = (int)(run[tid * 8 + j] & 0xFFFFFFFFu);
    }
}

// ---------------------------------------------------------------------------
// Exact refine + gather. One warp per row; 8 candidates, fp32 dots.
// ---------------------------------------------------------------------------
__global__ void __launch_bounds__(256)
refine_kernel(const float* __restrict__ cb, const float* __restrict__ x,
              float* __restrict__ out) {
    const int n = blockIdx.x * 8 + (threadIdx.x >> 5);
    const int lane = threadIdx.x & 31;

    float xr[16];
#pragma unroll
    for (int j = 0; j < 16; ++j) xr[j] = x[(size_t)n * DDIM + j * 32 + lane];

    float bv = 3.0e38f;
    int   bi = 0x7fffffff;
#pragma unroll
    for (int c = 0; c < NCAND; ++c) {
        const int k = g_cand[n * NCAND + c];
        const float* crow = cb + (size_t)k * DDIM;
        float s = 0.f;
#pragma unroll
        for (int j = 0; j < 16; ++j) s = fmaf(xr[j], __ldg(crow + j * 32 + lane), s);
#pragma unroll
        for (int o = 16; o > 0; o >>= 1) s += __shfl_xor_sync(0xffffffffu, s, o);
        float d2 = fmaf(-2.f, s, __ldg(&g_cnorm[k]));
        if (d2 < bv || (d2 == bv && k < bi)) { bv = d2; bi = k; }
    }

    const float* q = cb + (size_t)bi * DDIM;
#pragma unroll
    for (int j = 0; j < 16; ++j) {
        float qv = __ldg(q + j * 32 + lane);
        float xv = xr[j];
        out[(size_t)n * DDIM + j * 32 + lane] = (qv - xv) + xv;
    }
}

// ---------------------------------------------------------------------------
extern "C" void kernel_launch(void* const* d_in, const int* in_sizes, int n_in,
                              void* d_out, int out_size) {
    const float* inputs   = (const float*)d_in[0];
    const float* codebook = (const float*)d_in[1];
    float* out = (float*)d_out;

    cudaFuncSetAttribute(vq_coarse_kernel, cudaFuncAttributeMaxDynamicSharedMemorySize,
                         SMEM_TOTAL);

    split_inputs_kernel<<<4096, 256>>>(inputs);
    quant_codebook_kernel<<<KCODES, 128>>>(codebook);
    vq_coarse_kernel<<<N_ROWS / MT, 256, SMEM_TOTAL>>>();
    refine_kernel<<<N_ROWS / 8, 256>>>(codebook, inputs, out);
}

// round 10
// speedup vs baseline: 2.3676x; 1.3052x over previous
#include <cuda_runtime.h>
#include <cuda_fp16.h>
#include <cstdint>

// Problem constants
#define N_ROWS 32768
#define DDIM   512
#define KCODES 4096

// Coarse tiling (fp16 HMMA, f16 accumulate)
#define MT 128                 // rows per CTA
#define NT 128                 // codes per chunk
#define BK 64                  // K fp16 per SMEM tile (128B rows)
#define NCHUNKS (KCODES / NT)          // 32
#define KT_PER_CHUNK (DDIM / BK)       // 8
#define TOTAL_TILES (NCHUNKS * KT_PER_CHUNK)  // 256
#define NSTG 3
#define STAGE_BYTES 32768      // A 16KB + B 16KB
#define SMEM_TOTAL (NSTG * STAGE_BYTES)

#define NCAND 4

// ---------------- scratch ----------------
__device__ __half g_Ah[(size_t)N_ROWS * DDIM];
__device__ __half g_Ch[(size_t)KCODES * DDIM];
__device__ float g_cnorm[KCODES];
__device__ int   g_cand[N_ROWS * NCAND];

// ---------------- PTX helpers ----------------
__device__ __forceinline__ uint32_t smem_to_u32(const void* p) {
    uint32_t a;
    asm("{ .reg .u64 t; cvta.to.shared.u64 t, %1; cvt.u32.u64 %0, t; }" : "=r"(a) : "l"(p));
    return a;
}
__device__ __forceinline__ void cp_async16(uint32_t dst, const void* src) {
    asm volatile("cp.async.cg.shared.global [%0], [%1], 16;" :: "r"(dst), "l"(src) : "memory");
}
#define CP_COMMIT() asm volatile("cp.async.commit_group;" ::: "memory")
#define CP_WAIT(n)  asm volatile("cp.async.wait_group %0;" :: "n"(n) : "memory")

__device__ __forceinline__ void ldsm_x4(uint32_t& r0, uint32_t& r1, uint32_t& r2,
                                        uint32_t& r3, uint32_t addr) {
    asm volatile("ldmatrix.sync.aligned.m8n8.x4.shared.b16 {%0,%1,%2,%3}, [%4];"
                 : "=r"(r0), "=r"(r1), "=r"(r2), "=r"(r3) : "r"(addr));
}
// fp16 x fp16 -> fp16 accumulate (2 b32 regs hold 4 half values)
__device__ __forceinline__ void mma16816_f16(uint32_t* d, const uint32_t* a,
                                             uint32_t b0, uint32_t b1) {
    asm volatile(
        "mma.sync.aligned.m16n8k16.row.col.f16.f16.f16.f16 "
        "{%0,%1}, {%2,%3,%4,%5}, {%6,%7}, {%0,%1};"
        : "+r"(d[0]), "+r"(d[1])
        : "r"(a[0]), "r"(a[1]), "r"(a[2]), "r"(a[3]), "r"(b0), "r"(b1));
}
__device__ __forceinline__ uint32_t sw_off(int row, int chunk) {
    return (uint32_t)(row * 128 + ((chunk ^ (row & 7)) << 4));
}

// ---------------------------------------------------------------------------
// Precompute: inputs fp32 -> fp16 ; codebook -> fp16 + exact fp32 ||c||^2
// ---------------------------------------------------------------------------
__global__ void split_inputs_kernel(const float* __restrict__ src) {
    int n4 = N_ROWS * DDIM / 4;
    for (int i = blockIdx.x * blockDim.x + threadIdx.x; i < n4; i += gridDim.x * blockDim.x) {
        float4 v = reinterpret_cast<const float4*>(src)[i];
        __half h[4] = {__float2half_rn(v.x), __float2half_rn(v.y),
                       __float2half_rn(v.z), __float2half_rn(v.w)};
        reinterpret_cast<uint2*>(g_Ah)[i] = *reinterpret_cast<uint2*>(h);
    }
}
__global__ void quant_codebook_kernel(const float* __restrict__ cb) {
    int k = blockIdx.x;
    float4 v = reinterpret_cast<const float4*>(cb + (size_t)k * DDIM)[threadIdx.x];
    __half h[4] = {__float2half_rn(v.x), __float2half_rn(v.y),
                   __float2half_rn(v.z), __float2half_rn(v.w)};
    reinterpret_cast<uint2*>(g_Ch)[k * (DDIM / 4) + threadIdx.x] =
        *reinterpret_cast<uint2*>(h);
    float s = v.x * v.x + v.y * v.y + v.z * v.z + v.w * v.w;
#pragma unroll
    for (int o = 16; o > 0; o >>= 1) s += __shfl_xor_sync(0xffffffffu, s, o);
    __shared__ float ws[4];
    if ((threadIdx.x & 31) == 0) ws[threadIdx.x >> 5] = s;
    __syncthreads();
    if (threadIdx.x == 0) g_cnorm[k] = ws[0] + ws[1] + ws[2] + ws[3];
}

// ---------------------------------------------------------------------------
// Coarse pass: fp16 GEMM (f16 acc) + per-thread top-2 per row-slot.
// Grid 256 CTAs x 256 threads, 2 CTAs/SM. 8 warps (4m x 2n), warp tile 32x64.
// ---------------------------------------------------------------------------
__device__ __forceinline__ void issue_stage(uint32_t aBase, uint32_t bBase,
                                            int r0, int c0, int ks, int tid) {
#pragma unroll
    for (int i = 0; i < 4; ++i) {
        int idx = tid + i * 256;        // 0..1023
        int row = idx >> 3, ch = idx & 7;
        cp_async16(aBase + sw_off(row, ch),
                   g_Ah + (size_t)(r0 + row) * DDIM + ks + ch * 8);
    }
#pragma unroll
    for (int i = 0; i < 4; ++i) {
        int idx = tid + i * 256;
        int row = idx >> 3, ch = idx & 7;
        cp_async16(bBase + sw_off(row, ch),
                   g_Ch + (size_t)(c0 + row) * DDIM + ks + ch * 8);
    }
    CP_COMMIT();
}

__global__ void __launch_bounds__(256, 2)
vq_coarse_kernel() {
    extern __shared__ char smem[];
    const uint32_t sb = smem_to_u32(smem);
    const int tid  = threadIdx.x;
    const int lane = tid & 31;
    const int warp = tid >> 5;
    const int wm = warp >> 1;          // 0..3 (32 rows each)
    const int wn = warp & 1;           // 0..1 (64 codes each)
    const int r0 = blockIdx.x * MT;

    const int sub  = lane >> 3;
    const int lrow = (sub & 1) * 8 + (lane & 7);
    const int lchk = sub >> 1;

    uint32_t acc[2][8][2];             // f16x2 accumulators
#pragma unroll
    for (int mi = 0; mi < 2; ++mi)
#pragma unroll
        for (int n8 = 0; n8 < 8; ++n8) { acc[mi][n8][0] = 0u; acc[mi][n8][1] = 0u; }

    // per row-slot top-2 (4 slots: mi*2 + rowhalf)
    float v0[4], v1[4];
    int   i0[4], i1[4];
#pragma unroll
    for (int s = 0; s < 4; ++s) { v0[s] = v1[s] = 3.0e38f; i0[s] = i1[s] = 0x7fffffff; }

    issue_stage(sb, sb + 16384, r0, 0, 0, tid);
    issue_stage(sb + STAGE_BYTES, sb + STAGE_BYTES + 16384, r0, 0, BK, tid);

#pragma unroll 1
    for (int t = 0; t < TOTAL_TILES; ++t) {
        const int chunk = t >> 3;
        const int kt = t & 7;

        if (t == TOTAL_TILES - 1) { CP_WAIT(0); } else { CP_WAIT(1); }
        __syncthreads();

        if (t + 2 < TOTAL_TILES) {
            const int t2 = t + 2;
            const int s2 = t2 % NSTG;
            issue_stage(sb + s2 * STAGE_BYTES, sb + s2 * STAGE_BYTES + 16384,
                        r0, (t2 >> 3) * NT, (t2 & 7) * BK, tid);
        }

        const uint32_t aBase = sb + (t % NSTG) * STAGE_BYTES;
        const uint32_t bBase = aBase + 16384;
#pragma unroll
        for (int kk = 0; kk < 4; ++kk) {
            uint32_t a[2][4];
#pragma unroll
            for (int mi = 0; mi < 2; ++mi)
                ldsm_x4(a[mi][0], a[mi][1], a[mi][2], a[mi][3],
                        aBase + sw_off(wm * 32 + mi * 16 + lrow, kk * 2 + lchk));
            uint32_t bfr[4][4];
#pragma unroll
            for (int ni = 0; ni < 4; ++ni)
                ldsm_x4(bfr[ni][0], bfr[ni][1], bfr[ni][2], bfr[ni][3],
                        bBase + sw_off(wn * 64 + ni * 16 + lrow, kk * 2 + lchk));
#pragma unroll
            for (int mi = 0; mi < 2; ++mi)
#pragma unroll
                for (int n8 = 0; n8 < 8; ++n8)
                    mma16816_f16(acc[mi][n8], a[mi],
                                 bfr[n8 >> 1][n8 & 1], bfr[n8 >> 1][(n8 & 1) + 2]);
        }

        if (kt == KT_PER_CHUNK - 1) {
            const int c0 = chunk * NT;
#pragma unroll
            for (int n8 = 0; n8 < 8; ++n8) {
                const int col = c0 + wn * 64 + n8 * 8 + 2 * (lane & 3);
                const float cn0 = __ldg(&g_cnorm[col]);
                const float cn1 = __ldg(&g_cnorm[col + 1]);
#pragma unroll
                for (int mi = 0; mi < 2; ++mi) {
#pragma unroll
                    for (int r = 0; r < 2; ++r) {      // row-half (reg index)
                        const int slot = mi * 2 + r;
                        float2 f = __half22float2(
                            *reinterpret_cast<__half2*>(&acc[mi][n8][r]));
                        float d0 = fmaf(-2.f, f.x, cn0);
                        float d1 = fmaf(-2.f, f.y, cn1);
                        if (d0 < v1[slot]) {
                            if (d0 < v0[slot]) {
                                v1[slot] = v0[slot]; i1[slot] = i0[slot];
                                v0[slot] = d0;       i0[slot] = col;
                            } else { v1[slot] = d0; i1[slot] = col; }
                        }
                        if (d1 < v1[slot]) {
                            if (d1 < v0[slot]) {
                                v1[slot] = v0[slot]; i1[slot] = i0[slot];
                                v0[slot] = d1;       i0[slot] = col + 1;
                            } else { v1[slot] = d1; i1[slot] = col + 1; }
                        }
                        acc[mi][n8][r] = 0u;
                    }
                }
            }
        }
    }

    // Merge 8 threads x 2 entries per row -> global top-4 per row
    __syncthreads();
    float* mv = reinterpret_cast<float*>(smem);            // [128][16]
    int*   md = reinterpret_cast<int*>(smem + 8192);       // [128][16]
#pragma unroll
    for (int slot = 0; slot < 4; ++slot) {
        const int mi = slot >> 1, rh = slot & 1;
        const int row = wm * 32 + mi * 16 + rh * 8 + (lane >> 2);
        const int col = wn * 8 + (lane & 3) * 2;
        mv[row * 16 + col]     = v0[slot];
        md[row * 16 + col]     = i0[slot];
        mv[row * 16 + col + 1] = v1[slot];
        md[row * 16 + col + 1] = i1[slot];
    }
    __syncthreads();
    if (tid < MT) {
        float tv[4] = {3.0e38f, 3.0e38f, 3.0e38f, 3.0e38f};
        int   ti[4] = {0x7fffffff, 0x7fffffff, 0x7fffffff, 0x7fffffff};
#pragma unroll 4
        for (int e = 0; e < 16; ++e) {
            float v = mv[tid * 16 + e];
            int   d = md[tid * 16 + e];
            if (v < tv[3] || (v == tv[3] && d < ti[3])) {
                tv[3] = v; ti[3] = d;
#pragma unroll
                for (int j = 3; j >= 1; --j) {
                    if (tv[j] < tv[j-1] || (tv[j] == tv[j-1] && ti[j] < ti[j-1])) {
                        float fv = tv[j]; tv[j] = tv[j-1]; tv[j-1] = fv;
                        int   fi = ti[j]; ti[j] = ti[j-1]; ti[j-1] = fi;
                    }
                }
            }
        }
#pragma unroll
        for (int j = 0; j < 4; ++j) g_cand[(r0 + tid) * NCAND + j] = ti[j];
    }
}

// ---------------------------------------------------------------------------
// Exact refine + gather. One warp per row; 4 candidates, fp32 dots.
// ---------------------------------------------------------------------------
__global__ void __launch_bounds__(256)
refine_kernel(const float* __restrict__ cb, const float* __restrict__ x,
              float* __restrict__ out) {
    const int n = blockIdx.x * 8 + (threadIdx.x >> 5);
    const int lane = threadIdx.x & 31;

    float xr[16];
#pragma unroll
    for (int j = 0; j < 16; ++j) xr[j] = x[(size_t)n * DDIM + j * 32 + lane];

    float bv = 3.0e38f;
    int   bi = 0x7fffffff;
#pragma unroll
    for (int c = 0; c < NCAND; ++c) {
        const int k = g_cand[n * NCAND + c];
        const float* crow = cb + (size_t)k * DDIM;
        float s = 0.f;
#pragma unroll
        for (int j = 0; j < 16; ++j) s = fmaf(xr[j], __ldg(crow + j * 32 + lane), s);
#pragma unroll
        for (int o = 16; o > 0; o >>= 1) s += __shfl_xor_sync(0xffffffffu, s, o);
        float d2 = fmaf(-2.f, s, __ldg(&g_cnorm[k]));
        if (d2 < bv || (d2 == bv && k < bi)) { bv = d2; bi = k; }
    }

    const float* q = cb + (size_t)bi * DDIM;
#pragma unroll
    for (int j = 0; j < 16; ++j) {
        float qv = __ldg(q + j * 32 + lane);
        float xv = xr[j];
        out[(size_t)n * DDIM + j * 32 + lane] = (qv - xv) + xv;
    }
}

// ---------------------------------------------------------------------------
extern "C" void kernel_launch(void* const* d_in, const int* in_sizes, int n_in,
                              void* d_out, int out_size) {
    const float* inputs   = (const float*)d_in[0];
    const float* codebook = (const float*)d_in[1];
    float* out = (float*)d_out;

    cudaFuncSetAttribute(vq_coarse_kernel, cudaFuncAttributeMaxDynamicSharedMemorySize,
                         SMEM_TOTAL);

    split_inputs_kernel<<<4096, 256>>>(inputs);
    quant_codebook_kernel<<<KCODES, 128>>>(codebook);
    vq_coarse_kernel<<<N_ROWS / MT, 256, SMEM_TOTAL>>>();
    refine_kernel<<<N_ROWS / 8, 256>>>(codebook, inputs, out);
}

// round 11
// speedup vs baseline: 2.3925x; 1.0105x over previous
#include <cuda_runtime.h>
#include <cuda_fp16.h>
#include <cstdint>

// Problem constants
#define N_ROWS 32768
#define DDIM   512
#define KCODES 4096

// Coarse tiling (fp16 HMMA, f16 accumulate) — proven round-5/10 skeleton
#define MT 128                 // rows per CTA
#define NT 128                 // codes per chunk
#define BK 64                  // K fp16 per SMEM tile (128B rows)
#define NCHUNKS (KCODES / NT)          // 32
#define KT_PER_CHUNK (DDIM / BK)       // 8
#define TOTAL_TILES (NCHUNKS * KT_PER_CHUNK)  // 256
#define NSTG 3
#define STAGE_BYTES 32768      // A 16KB + B 16KB
#define SMEM_TOTAL (NSTG * STAGE_BYTES)

#define NCAND 4

// ---------------- scratch ----------------
__device__ __half g_Ah[(size_t)N_ROWS * DDIM];
__device__ __half g_Ch[(size_t)KCODES * DDIM];
__device__ float g_cnorm[KCODES];

// ---------------- PTX helpers ----------------
__device__ __forceinline__ uint32_t smem_to_u32(const void* p) {
    uint32_t a;
    asm("{ .reg .u64 t; cvta.to.shared.u64 t, %1; cvt.u32.u64 %0, t; }" : "=r"(a) : "l"(p));
    return a;
}
__device__ __forceinline__ void cp_async16(uint32_t dst, const void* src) {
    asm volatile("cp.async.cg.shared.global [%0], [%1], 16;" :: "r"(dst), "l"(src) : "memory");
}
#define CP_COMMIT() asm volatile("cp.async.commit_group;" ::: "memory")
#define CP_WAIT(n)  asm volatile("cp.async.wait_group %0;" :: "n"(n) : "memory")

__device__ __forceinline__ void ldsm_x4(uint32_t& r0, uint32_t& r1, uint32_t& r2,
                                        uint32_t& r3, uint32_t addr) {
    asm volatile("ldmatrix.sync.aligned.m8n8.x4.shared.b16 {%0,%1,%2,%3}, [%4];"
                 : "=r"(r0), "=r"(r1), "=r"(r2), "=r"(r3) : "r"(addr));
}
// fp16 x fp16 -> fp16 accumulate
__device__ __forceinline__ void mma16816_f16(uint32_t* d, const uint32_t* a,
                                             uint32_t b0, uint32_t b1) {
    asm volatile(
        "mma.sync.aligned.m16n8k16.row.col.f16.f16.f16.f16 "
        "{%0,%1}, {%2,%3,%4,%5}, {%6,%7}, {%0,%1};"
        : "+r"(d[0]), "+r"(d[1])
        : "r"(a[0]), "r"(a[1]), "r"(a[2]), "r"(a[3]), "r"(b0), "r"(b1));
}
__device__ __forceinline__ uint32_t sw_off(int row, int chunk) {
    return (uint32_t)(row * 128 + ((chunk ^ (row & 7)) << 4));
}

// ---------------------------------------------------------------------------
// Prep (merged): blocks 0..4095 quantize codebook rows + cnorm;
// blocks 4096..36863 convert input rows fp32 -> fp16.  128 thr, 1 row each.
// ---------------------------------------------------------------------------
__global__ void prep_kernel(const float* __restrict__ inp, const float* __restrict__ cb) {
    const int bid = blockIdx.x;
    if (bid < KCODES) {
        const int k = bid;
        float4 v = reinterpret_cast<const float4*>(cb + (size_t)k * DDIM)[threadIdx.x];
        __half h[4] = {__float2half_rn(v.x), __float2half_rn(v.y),
                       __float2half_rn(v.z), __float2half_rn(v.w)};
        reinterpret_cast<uint2*>(g_Ch)[k * (DDIM / 4) + threadIdx.x] =
            *reinterpret_cast<uint2*>(h);
        float s = v.x * v.x + v.y * v.y + v.z * v.z + v.w * v.w;
#pragma unroll
        for (int o = 16; o > 0; o >>= 1) s += __shfl_xor_sync(0xffffffffu, s, o);
        __shared__ float ws[4];
        if ((threadIdx.x & 31) == 0) ws[threadIdx.x >> 5] = s;
        __syncthreads();
        if (threadIdx.x == 0) g_cnorm[k] = ws[0] + ws[1] + ws[2] + ws[3];
    } else {
        const int n = bid - KCODES;
        float4 v = reinterpret_cast<const float4*>(inp + (size_t)n * DDIM)[threadIdx.x];
        __half h[4] = {__float2half_rn(v.x), __float2half_rn(v.y),
                       __float2half_rn(v.z), __float2half_rn(v.w)};
        reinterpret_cast<uint2*>(g_Ah)[n * (DDIM / 4) + threadIdx.x] =
            *reinterpret_cast<uint2*>(h);
    }
}

// ---------------------------------------------------------------------------
// Coarse pass + fused exact refine.
// Grid 256 CTAs x 256 threads, 2 CTAs/SM. 8 warps (4m x 2n), warp tile 32x64.
// ---------------------------------------------------------------------------
__device__ __forceinline__ void issue_stage(uint32_t aBase, uint32_t bBase,
                                            int r0, int c0, int ks, int tid) {
#pragma unroll
    for (int i = 0; i < 4; ++i) {
        int idx = tid + i * 256;        // 0..1023
        int row = idx >> 3, ch = idx & 7;
        cp_async16(aBase + sw_off(row, ch),
                   g_Ah + (size_t)(r0 + row) * DDIM + ks + ch * 8);
    }
#pragma unroll
    for (int i = 0; i < 4; ++i) {
        int idx = tid + i * 256;
        int row = idx >> 3, ch = idx & 7;
        cp_async16(bBase + sw_off(row, ch),
                   g_Ch + (size_t)(c0 + row) * DDIM + ks + ch * 8);
    }
    CP_COMMIT();
}

__global__ void __launch_bounds__(256, 2)
vq_fused_kernel(const float* __restrict__ cb, const float* __restrict__ x,
                float* __restrict__ out) {
    extern __shared__ char smem[];
    const uint32_t sb = smem_to_u32(smem);
    const int tid  = threadIdx.x;
    const int lane = tid & 31;
    const int warp = tid >> 5;
    const int wm = warp >> 1;          // 0..3 (32 rows each)
    const int wn = warp & 1;           // 0..1 (64 codes each)
    const int r0 = blockIdx.x * MT;

    const int sub  = lane >> 3;
    const int lrow = (sub & 1) * 8 + (lane & 7);
    const int lchk = sub >> 1;

    uint32_t acc[2][8][2];             // f16x2 accumulators
#pragma unroll
    for (int mi = 0; mi < 2; ++mi)
#pragma unroll
        for (int n8 = 0; n8 < 8; ++n8) { acc[mi][n8][0] = 0u; acc[mi][n8][1] = 0u; }

    // per row-slot top-2 (4 slots: mi*2 + rowhalf)
    float v0[4], v1[4];
    int   i0[4], i1[4];
#pragma unroll
    for (int s = 0; s < 4; ++s) { v0[s] = v1[s] = 3.0e38f; i0[s] = i1[s] = 0x7fffffff; }

    issue_stage(sb, sb + 16384, r0, 0, 0, tid);
    issue_stage(sb + STAGE_BYTES, sb + STAGE_BYTES + 16384, r0, 0, BK, tid);

#pragma unroll 1
    for (int t = 0; t < TOTAL_TILES; ++t) {
        const int chunk = t >> 3;
        const int kt = t & 7;

        if (t == TOTAL_TILES - 1) { CP_WAIT(0); } else { CP_WAIT(1); }
        __syncthreads();

        if (t + 2 < TOTAL_TILES) {
            const int t2 = t + 2;
            const int s2 = t2 % NSTG;
            issue_stage(sb + s2 * STAGE_BYTES, sb + s2 * STAGE_BYTES + 16384,
                        r0, (t2 >> 3) * NT, (t2 & 7) * BK, tid);
        }

        const uint32_t aBase = sb + (t % NSTG) * STAGE_BYTES;
        const uint32_t bBase = aBase + 16384;
#pragma unroll
        for (int kk = 0; kk < 4; ++kk) {
            uint32_t a[2][4];
#pragma unroll
            for (int mi = 0; mi < 2; ++mi)
                ldsm_x4(a[mi][0], a[mi][1], a[mi][2], a[mi][3],
                        aBase + sw_off(wm * 32 + mi * 16 + lrow, kk * 2 + lchk));
            uint32_t bfr[4][4];
#pragma unroll
            for (int ni = 0; ni < 4; ++ni)
                ldsm_x4(bfr[ni][0], bfr[ni][1], bfr[ni][2], bfr[ni][3],
                        bBase + sw_off(wn * 64 + ni * 16 + lrow, kk * 2 + lchk));
#pragma unroll
            for (int mi = 0; mi < 2; ++mi)
#pragma unroll
                for (int n8 = 0; n8 < 8; ++n8)
                    mma16816_f16(acc[mi][n8], a[mi],
                                 bfr[n8 >> 1][n8 & 1], bfr[n8 >> 1][(n8 & 1) + 2]);
        }

        if (kt == KT_PER_CHUNK - 1) {
            const int c0 = chunk * NT;
#pragma unroll
            for (int n8 = 0; n8 < 8; ++n8) {
                const int col = c0 + wn * 64 + n8 * 8 + 2 * (lane & 3);
                const float cn0 = __ldg(&g_cnorm[col]);
                const float cn1 = __ldg(&g_cnorm[col + 1]);
#pragma unroll
                for (int mi = 0; mi < 2; ++mi) {
#pragma unroll
                    for (int r = 0; r < 2; ++r) {
                        const int slot = mi * 2 + r;
                        float2 f = __half22float2(
                            *reinterpret_cast<__half2*>(&acc[mi][n8][r]));
                        float d0 = fmaf(-2.f, f.x, cn0);
                        float d1 = fmaf(-2.f, f.y, cn1);
                        if (d0 < v1[slot]) {
                            if (d0 < v0[slot]) {
                                v1[slot] = v0[slot]; i1[slot] = i0[slot];
                                v0[slot] = d0;       i0[slot] = col;
                            } else { v1[slot] = d0; i1[slot] = col; }
                        }
                        if (d1 < v1[slot]) {
                            if (d1 < v0[slot]) {
                                v1[slot] = v0[slot]; i1[slot] = i0[slot];
                                v0[slot] = d1;       i0[slot] = col + 1;
                            } else { v1[slot] = d1; i1[slot] = col + 1; }
                        }
                        acc[mi][n8][r] = 0u;
                    }
                }
            }
        }
    }

    // ---- Merge 8 threads x 2 entries per row -> top-4 per row (in smem) ----
    __syncthreads();
    float* mv   = reinterpret_cast<float*>(smem);            // [128][16]
    int*   md   = reinterpret_cast<int*>(smem + 8192);       // [128][16]
    int*   cand = reinterpret_cast<int*>(smem + 16384);      // [128][4]
#pragma unroll
    for (int slot = 0; slot < 4; ++slot) {
        const int mi = slot >> 1, rh = slot & 1;
        const int row = wm * 32 + mi * 16 + rh * 8 + (lane >> 2);
        const int col = wn * 8 + (lane & 3) * 2;
        mv[row * 16 + col]     = v0[slot];
        md[row * 16 + col]     = i0[slot];
        mv[row * 16 + col + 1] = v1[slot];
        md[row * 16 + col + 1] = i1[slot];
    }
    __syncthreads();
    if (tid < MT) {
        float tv[4] = {3.0e38f, 3.0e38f, 3.0e38f, 3.0e38f};
        int   ti[4] = {0x7fffffff, 0x7fffffff, 0x7fffffff, 0x7fffffff};
#pragma unroll 4
        for (int e = 0; e < 16; ++e) {
            float v = mv[tid * 16 + e];
            int   d = md[tid * 16 + e];
            if (v < tv[3] || (v == tv[3] && d < ti[3])) {
                tv[3] = v; ti[3] = d;
#pragma unroll
                for (int j = 3; j >= 1; --j) {
                    if (tv[j] < tv[j-1] || (tv[j] == tv[j-1] && ti[j] < ti[j-1])) {
                        float fv = tv[j]; tv[j] = tv[j-1]; tv[j-1] = fv;
                        int   fi = ti[j]; ti[j] = ti[j-1]; ti[j-1] = fi;
                    }
                }
            }
        }
#pragma unroll
        for (int j = 0; j < 4; ++j) cand[tid * 4 + j] = ti[j];
    }
    __syncthreads();

    // ---- Fused exact refine + gather: warp w refines rows [w*16, w*16+16) ----
#pragma unroll 1
    for (int rr = 0; rr < 16; ++rr) {
        const int row = warp * 16 + rr;
        const int n = r0 + row;

        float xr[16];
#pragma unroll
        for (int j = 0; j < 16; ++j) xr[j] = x[(size_t)n * DDIM + j * 32 + lane];

        float bv = 3.0e38f;
        int   bi = 0x7fffffff;
#pragma unroll
        for (int c = 0; c < NCAND; ++c) {
            const int k = cand[row * 4 + c];
            const float* crow = cb + (size_t)k * DDIM;
            float s = 0.f;
#pragma unroll
            for (int j = 0; j < 16; ++j) s = fmaf(xr[j], __ldg(crow + j * 32 + lane), s);
#pragma unroll
            for (int o = 16; o > 0; o >>= 1) s += __shfl_xor_sync(0xffffffffu, s, o);
            float d2 = fmaf(-2.f, s, __ldg(&g_cnorm[k]));
            if (d2 < bv || (d2 == bv && k < bi)) { bv = d2; bi = k; }
        }

        const float* q = cb + (size_t)bi * DDIM;
#pragma unroll
        for (int j = 0; j < 16; ++j) {
            float qv = __ldg(q + j * 32 + lane);
            float xv = xr[j];
            out[(size_t)n * DDIM + j * 32 + lane] = (qv - xv) + xv;
        }
    }
}

// ---------------------------------------------------------------------------
extern "C" void kernel_launch(void* const* d_in, const int* in_sizes, int n_in,
                              void* d_out, int out_size) {
    const float* inputs   = (const float*)d_in[0];
    const float* codebook = (const float*)d_in[1];
    float* out = (float*)d_out;

    cudaFuncSetAttribute(vq_fused_kernel, cudaFuncAttributeMaxDynamicSharedMemorySize,
                         SMEM_TOTAL);

    prep_kernel<<<KCODES + N_ROWS, 128>>>(inputs, codebook);
    vq_fused_kernel<<<N_ROWS / MT, 256, SMEM_TOTAL>>>(codebook, inputs, out);
}

// round 13
// speedup vs baseline: 2.5590x; 1.0696x over previous
#include <cuda_runtime.h>
#include <cuda_fp16.h>
#include <cstdint>

// Problem constants
#define N_ROWS 32768
#define DDIM   512
#define KCODES 4096

// Coarse tiling (fp16 HMMA, f16 accumulate)
#define MT 128                 // rows per CTA
#define NT 128                 // codes per chunk
#define BK 64                  // K fp16 per SMEM tile (128B rows)
#define NCHUNKS (KCODES / NT)          // 32
#define STAGE_BYTES 32768      // A 16KB + B 16KB
#define SMEM_TOTAL (2 * STAGE_BYTES)   // 65536

#define NCAND 4

// ---------------- scratch ----------------
__device__ __half g_Ah[(size_t)N_ROWS * DDIM];
__device__ __half g_Ch[(size_t)KCODES * DDIM];
__device__ float g_cnorm[KCODES];

// ---------------- PTX helpers ----------------
__device__ __forceinline__ uint32_t smem_to_u32(const void* p) {
    uint32_t a;
    asm("{ .reg .u64 t; cvta.to.shared.u64 t, %1; cvt.u32.u64 %0, t; }" : "=r"(a) : "l"(p));
    return a;
}
__device__ __forceinline__ void cp_async16(uint32_t dst, const void* src) {
    asm volatile("cp.async.cg.shared.global [%0], [%1], 16;" :: "r"(dst), "l"(src) : "memory");
}
#define CP_COMMIT() asm volatile("cp.async.commit_group;" ::: "memory")
#define CP_WAIT(n)  asm volatile("cp.async.wait_group %0;" :: "n"(n) : "memory")

__device__ __forceinline__ void ldsm_x4(uint32_t& r0, uint32_t& r1, uint32_t& r2,
                                        uint32_t& r3, uint32_t addr) {
    asm volatile("ldmatrix.sync.aligned.m8n8.x4.shared.b16 {%0,%1,%2,%3}, [%4];"
                 : "=r"(r0), "=r"(r1), "=r"(r2), "=r"(r3) : "r"(addr));
}
// fp16 x fp16 -> fp16 accumulate
__device__ __forceinline__ void mma16816_f16(uint32_t* d, const uint32_t* a,
                                             uint32_t b0, uint32_t b1) {
    asm volatile(
        "mma.sync.aligned.m16n8k16.row.col.f16.f16.f16.f16 "
        "{%0,%1}, {%2,%3,%4,%5}, {%6,%7}, {%0,%1};"
        : "+r"(d[0]), "+r"(d[1])
        : "r"(a[0]), "r"(a[1]), "r"(a[2]), "r"(a[3]), "r"(b0), "r"(b1));
}

// ---------------------------------------------------------------------------
// Prep (merged): blocks 0..4095 quantize codebook rows + cnorm;
// blocks 4096..36863 convert input rows fp32 -> fp16.  128 thr, 1 row each.
// ---------------------------------------------------------------------------
__global__ void prep_kernel(const float* __restrict__ inp, const float* __restrict__ cb) {
    const int bid = blockIdx.x;
    if (bid < KCODES) {
        const int k = bid;
        float4 v = reinterpret_cast<const float4*>(cb + (size_t)k * DDIM)[threadIdx.x];
        __half h[4] = {__float2half_rn(v.x), __float2half_rn(v.y),
                       __float2half_rn(v.z), __float2half_rn(v.w)};
        reinterpret_cast<uint2*>(g_Ch)[k * (DDIM / 4) + threadIdx.x] =
            *reinterpret_cast<uint2*>(h);
        float s = v.x * v.x + v.y * v.y + v.z * v.z + v.w * v.w;
#pragma unroll
        for (int o = 16; o > 0; o >>= 1) s += __shfl_xor_sync(0xffffffffu, s, o);
        __shared__ float ws[4];
        if ((threadIdx.x & 31) == 0) ws[threadIdx.x >> 5] = s;
        __syncthreads();
        if (threadIdx.x == 0) g_cnorm[k] = ws[0] + ws[1] + ws[2] + ws[3];
    } else {
        const int n = bid - KCODES;
        float4 v = reinterpret_cast<const float4*>(inp + (size_t)n * DDIM)[threadIdx.x];
        __half h[4] = {__float2half_rn(v.x), __float2half_rn(v.y),
                       __float2half_rn(v.z), __float2half_rn(v.w)};
        reinterpret_cast<uint2*>(g_Ah)[n * (DDIM / 4) + threadIdx.x] =
            *reinterpret_cast<uint2*>(h);
    }
}

// ---------------------------------------------------------------------------
// Coarse pass + fused exact refine.
// Grid 256 CTAs x 256 threads, 2 CTAs/SM. 8 warps (4m x 2n), warp tile 32x64.
// 2-stage cp.async pipeline, kt fully unrolled, immediate-offset addressing.
// Per-slot TOP-2 (proven safe) -> top-4 per row -> exact fp32 refine.
// ---------------------------------------------------------------------------
__global__ void __launch_bounds__(256, 2)
vq_fused_kernel(const float* __restrict__ cb, const float* __restrict__ x,
                float* __restrict__ out) {
    extern __shared__ char smem[];
    const uint32_t sb = smem_to_u32(smem);
    const int tid  = threadIdx.x;
    const int lane = tid & 31;
    const int warp = tid >> 5;
    const int wm = warp >> 1;          // 0..3 (32 rows each)
    const int wn = warp & 1;           // 0..1 (64 codes each)
    const int r0 = blockIdx.x * MT;

    const int sub  = lane >> 3;
    const int lrow = (sub & 1) * 8 + (lane & 7);
    const int lchk = sub >> 1;

    // ---- loader constants ----
    const int ldr = tid >> 3;          // 0..31
    const int ldc = tid & 7;
    const uint32_t swl = (uint32_t)(ldr * 128 + ((ldc ^ (ldr & 7)) << 4));
    const uint32_t dA[2] = { sb + swl, sb + STAGE_BYTES + swl };
    const uint32_t dB[2] = { sb + 16384 + swl, sb + STAGE_BYTES + 16384 + swl };
    const char* pA = (const char*)g_Ah + ((size_t)(r0 + ldr) * DDIM + ldc * 8) * 2;
    const char* pB = (const char*)g_Ch + ((size_t)ldr * DDIM + ldc * 8) * 2;

    // ---- LDSM base addresses (addr = base ^ (kk<<5)) ----
    uint32_t fullA[2][2], fullB[2][4];
#pragma unroll
    for (int mi = 0; mi < 2; ++mi) {
        int r = wm * 32 + mi * 16 + lrow;
        uint32_t b = (uint32_t)(r * 128 + (((r & 7) ^ lchk) << 4));
        fullA[0][mi] = sb + b;
        fullA[1][mi] = sb + STAGE_BYTES + b;
    }
#pragma unroll
    for (int ni = 0; ni < 4; ++ni) {
        int r = wn * 64 + ni * 16 + lrow;
        uint32_t b = (uint32_t)(r * 128 + (((r & 7) ^ lchk) << 4));
        fullB[0][ni] = sb + 16384 + b;
        fullB[1][ni] = sb + STAGE_BYTES + 16384 + b;
    }

    uint32_t acc[2][8][2];
#pragma unroll
    for (int mi = 0; mi < 2; ++mi)
#pragma unroll
        for (int n8 = 0; n8 < 8; ++n8) { acc[mi][n8][0] = 0u; acc[mi][n8][1] = 0u; }

    // per row-slot TOP-2 (slot = mi*2 + rowhalf)
    float v0[4], v1[4];
    int   i0[4], i1[4];
#pragma unroll
    for (int s = 0; s < 4; ++s) { v0[s] = v1[s] = 3.0e38f; i0[s] = i1[s] = 0x7fffffff; }

    // prologue: tile (chunk 0, kt 0) -> stage 0
#pragma unroll
    for (int i = 0; i < 4; ++i) {
        cp_async16(dA[0] + i * 4096, pA + i * 32768);
        cp_async16(dB[0] + i * 4096, pB + i * 32768);
    }
    CP_COMMIT();

#pragma unroll 1
    for (int chunk = 0; chunk < NCHUNKS; ++chunk) {
#pragma unroll
        for (int kt = 0; kt < 8; ++kt) {
            CP_WAIT(0);
            __syncthreads();

            // issue next tile into the other stage
            if (kt < 7) {
#pragma unroll
                for (int i = 0; i < 4; ++i) {
                    cp_async16(dA[(kt + 1) & 1] + i * 4096,
                               pA + (kt + 1) * 128 + i * 32768);
                    cp_async16(dB[(kt + 1) & 1] + i * 4096,
                               pB + (kt + 1) * 128 + i * 32768);
                }
                CP_COMMIT();
            } else if (chunk < NCHUNKS - 1) {
                const char* pBn = pB + 131072;
#pragma unroll
                for (int i = 0; i < 4; ++i) {
                    cp_async16(dA[0] + i * 4096, pA + i * 32768);
                    cp_async16(dB[0] + i * 4096, pBn + i * 32768);
                }
                CP_COMMIT();
            }

            // compute on stage kt&1
            {
                const int s = kt & 1;
#pragma unroll
                for (int kk = 0; kk < 4; ++kk) {
                    uint32_t a[2][4];
#pragma unroll
                    for (int mi = 0; mi < 2; ++mi)
                        ldsm_x4(a[mi][0], a[mi][1], a[mi][2], a[mi][3],
                                fullA[s][mi] ^ (uint32_t)(kk << 5));
                    uint32_t bf[4][4];
#pragma unroll
                    for (int ni = 0; ni < 4; ++ni)
                        ldsm_x4(bf[ni][0], bf[ni][1], bf[ni][2], bf[ni][3],
                                fullB[s][ni] ^ (uint32_t)(kk << 5));
#pragma unroll
                    for (int mi = 0; mi < 2; ++mi)
#pragma unroll
                        for (int n8 = 0; n8 < 8; ++n8)
                            mma16816_f16(acc[mi][n8], a[mi],
                                         bf[n8 >> 1][n8 & 1], bf[n8 >> 1][(n8 & 1) + 2]);
                }
            }

            // chunk epilogue: TOP-2 per slot
            if (kt == 7) {
                const int c0 = chunk * NT;
#pragma unroll
                for (int n8 = 0; n8 < 8; ++n8) {
                    const int col = c0 + wn * 64 + n8 * 8 + 2 * (lane & 3);
                    const float cn0 = __ldg(&g_cnorm[col]);
                    const float cn1 = __ldg(&g_cnorm[col + 1]);
#pragma unroll
                    for (int mi = 0; mi < 2; ++mi) {
#pragma unroll
                        for (int r = 0; r < 2; ++r) {
                            const int slot = mi * 2 + r;
                            float2 f = __half22float2(
                                *reinterpret_cast<__half2*>(&acc[mi][n8][r]));
                            float d0 = fmaf(-2.f, f.x, cn0);
                            float d1 = fmaf(-2.f, f.y, cn1);
                            if (d0 < v1[slot]) {
                                if (d0 < v0[slot]) {
                                    v1[slot] = v0[slot]; i1[slot] = i0[slot];
                                    v0[slot] = d0;       i0[slot] = col;
                                } else { v1[slot] = d0; i1[slot] = col; }
                            }
                            if (d1 < v1[slot]) {
                                if (d1 < v0[slot]) {
                                    v1[slot] = v0[slot]; i1[slot] = i0[slot];
                                    v0[slot] = d1;       i0[slot] = col + 1;
                                } else { v1[slot] = d1; i1[slot] = col + 1; }
                            }
                            acc[mi][n8][r] = 0u;
                        }
                    }
                }
            }
        }
        pB += 131072;   // next 128 codebook rows
    }

    // ---- Merge 8 threads x 2 entries per row -> top-4 per row (in smem) ----
    __syncthreads();
    float* mv   = reinterpret_cast<float*>(smem);            // [128][16]
    int*   md   = reinterpret_cast<int*>(smem + 8192);       // [128][16]
    int*   cand = reinterpret_cast<int*>(smem + 16384);      // [128][4]
#pragma unroll
    for (int slot = 0; slot < 4; ++slot) {
        const int mi = slot >> 1, rh = slot & 1;
        const int row = wm * 32 + mi * 16 + rh * 8 + (lane >> 2);
        const int col = wn * 8 + (lane & 3) * 2;
        mv[row * 16 + col]     = v0[slot];
        md[row * 16 + col]     = i0[slot];
        mv[row * 16 + col + 1] = v1[slot];
        md[row * 16 + col + 1] = i1[slot];
    }
    __syncthreads();
    if (tid < MT) {
        float tv[4] = {3.0e38f, 3.0e38f, 3.0e38f, 3.0e38f};
        int   ti[4] = {0x7fffffff, 0x7fffffff, 0x7fffffff, 0x7fffffff};
#pragma unroll 4
        for (int e = 0; e < 16; ++e) {
            float v = mv[tid * 16 + e];
            int   d = md[tid * 16 + e];
            if (v < tv[3] || (v == tv[3] && d < ti[3])) {
                tv[3] = v; ti[3] = d;
#pragma unroll
                for (int j = 3; j >= 1; --j) {
                    if (tv[j] < tv[j-1] || (tv[j] == tv[j-1] && ti[j] < ti[j-1])) {
                        float fv = tv[j]; tv[j] = tv[j-1]; tv[j-1] = fv;
                        int   fi = ti[j]; ti[j] = ti[j-1]; ti[j-1] = fi;
                    }
                }
            }
        }
#pragma unroll
        for (int j = 0; j < 4; ++j) cand[tid * 4 + j] = ti[j];
    }
    __syncthreads();

    // ---- Fused exact refine + gather: warp w refines rows [w*16, w*16+16) ----
#pragma unroll 1
    for (int rr = 0; rr < 16; ++rr) {
        const int row = warp * 16 + rr;
        const int n = r0 + row;

        float xr[16];
#pragma unroll
        for (int j = 0; j < 16; ++j) xr[j] = x[(size_t)n * DDIM + j * 32 + lane];

        float bv = 3.0e38f;
        int   bi = 0x7fffffff;
#pragma unroll
        for (int c = 0; c < NCAND; ++c) {
            const int k = cand[row * 4 + c];
            const float* crow = cb + (size_t)k * DDIM;
            float s = 0.f;
#pragma unroll
            for (int j = 0; j < 16; ++j) s = fmaf(xr[j], __ldg(crow + j * 32 + lane), s);
#pragma unroll
            for (int o = 16; o > 0; o >>= 1) s += __shfl_xor_sync(0xffffffffu, s, o);
            float d2 = fmaf(-2.f, s, __ldg(&g_cnorm[k]));
            if (d2 < bv || (d2 == bv && k < bi)) { bv = d2; bi = k; }
        }

        const float* q = cb + (size_t)bi * DDIM;
#pragma unroll
        for (int j = 0; j < 16; ++j) {
            float qv = __ldg(q + j * 32 + lane);
            float xv = xr[j];
            out[(size_t)n * DDIM + j * 32 + lane] = (qv - xv) + xv;
        }
    }
}

// ---------------------------------------------------------------------------
extern "C" void kernel_launch(void* const* d_in, const int* in_sizes, int n_in,
                              void* d_out, int out_size) {
    const float* inputs   = (const float*)d_in[0];
    const float* codebook = (const float*)d_in[1];
    float* out = (float*)d_out;

    cudaFuncSetAttribute(vq_fused_kernel, cudaFuncAttributeMaxDynamicSharedMemorySize,
                         SMEM_TOTAL);

    prep_kernel<<<KCODES + N_ROWS, 128>>>(inputs, codebook);
    vq_fused_kernel<<<N_ROWS / MT, 256, SMEM_TOTAL>>>(codebook, inputs, out);
}

// round 14
// speedup vs baseline: 2.5618x; 1.0011x over previous
#include <cuda_runtime.h>
#include <cuda_fp16.h>
#include <cstdint>

// Problem constants
#define N_ROWS 32768
#define DDIM   512
#define KCODES 4096

// Coarse tiling (fp16 HMMA, f16 accumulate)
#define MT 128                 // rows per CTA
#define NT 128                 // codes per chunk
#define BK 64                  // K fp16 per SMEM tile (128B rows)
#define NCHUNKS (KCODES / NT)          // 32
#define STAGE_BYTES 32768      // A 16KB + B 16KB
#define SMEM_TOTAL (2 * STAGE_BYTES)   // 65536

#define NCAND 4

// ---------------- scratch ----------------
__device__ __half g_Ah[(size_t)N_ROWS * DDIM];
__device__ __half g_Ch[(size_t)KCODES * DDIM];
__device__ float g_cnorm[KCODES];

// ---------------- PTX helpers ----------------
__device__ __forceinline__ uint32_t smem_to_u32(const void* p) {
    uint32_t a;
    asm("{ .reg .u64 t; cvta.to.shared.u64 t, %1; cvt.u32.u64 %0, t; }" : "=r"(a) : "l"(p));
    return a;
}
__device__ __forceinline__ void cp_async16(uint32_t dst, const void* src) {
    asm volatile("cp.async.cg.shared.global [%0], [%1], 16;" :: "r"(dst), "l"(src) : "memory");
}
#define CP_COMMIT() asm volatile("cp.async.commit_group;" ::: "memory")
#define CP_WAIT(n)  asm volatile("cp.async.wait_group %0;" :: "n"(n) : "memory")

__device__ __forceinline__ void ldsm_x4(uint32_t& r0, uint32_t& r1, uint32_t& r2,
                                        uint32_t& r3, uint32_t addr) {
    asm volatile("ldmatrix.sync.aligned.m8n8.x4.shared.b16 {%0,%1,%2,%3}, [%4];"
                 : "=r"(r0), "=r"(r1), "=r"(r2), "=r"(r3) : "r"(addr));
}
// fp16 x fp16 -> fp16 accumulate
__device__ __forceinline__ void mma16816_f16(uint32_t* d, const uint32_t* a,
                                             uint32_t b0, uint32_t b1) {
    asm volatile(
        "mma.sync.aligned.m16n8k16.row.col.f16.f16.f16.f16 "
        "{%0,%1}, {%2,%3,%4,%5}, {%6,%7}, {%0,%1};"
        : "+r"(d[0]), "+r"(d[1])
        : "r"(a[0]), "r"(a[1]), "r"(a[2]), "r"(a[3]), "r"(b0), "r"(b1));
}

// ---------------------------------------------------------------------------
// Prep (merged): blocks 0..4095 quantize codebook rows + cnorm;
// blocks 4096..36863 convert input rows fp32 -> fp16.  128 thr, 1 row each.
// ---------------------------------------------------------------------------
__global__ void prep_kernel(const float* __restrict__ inp, const float* __restrict__ cb) {
    const int bid = blockIdx.x;
    if (bid < KCODES) {
        const int k = bid;
        float4 v = reinterpret_cast<const float4*>(cb + (size_t)k * DDIM)[threadIdx.x];
        __half h[4] = {__float2half_rn(v.x), __float2half_rn(v.y),
                       __float2half_rn(v.z), __float2half_rn(v.w)};
        reinterpret_cast<uint2*>(g_Ch)[k * (DDIM / 4) + threadIdx.x] =
            *reinterpret_cast<uint2*>(h);
        float s = v.x * v.x + v.y * v.y + v.z * v.z + v.w * v.w;
#pragma unroll
        for (int o = 16; o > 0; o >>= 1) s += __shfl_xor_sync(0xffffffffu, s, o);
        __shared__ float ws[4];
        if ((threadIdx.x & 31) == 0) ws[threadIdx.x >> 5] = s;
        __syncthreads();
        if (threadIdx.x == 0) g_cnorm[k] = ws[0] + ws[1] + ws[2] + ws[3];
    } else {
        const int n = bid - KCODES;
        float4 v = reinterpret_cast<const float4*>(inp + (size_t)n * DDIM)[threadIdx.x];
        __half h[4] = {__float2half_rn(v.x), __float2half_rn(v.y),
                       __float2half_rn(v.z), __float2half_rn(v.w)};
        reinterpret_cast<uint2*>(g_Ah)[n * (DDIM / 4) + threadIdx.x] =
            *reinterpret_cast<uint2*>(h);
    }
}

// ---------------------------------------------------------------------------
// Coarse pass + fused exact refine.
// Grid 256 CTAs x 256 threads, 2 CTAs/SM. 8 warps (4m x 2n), warp tile 32x64.
// 2-stage cp.async pipeline, kt fully unrolled, immediate-offset addressing.
// Fragment loads software-pipelined (LDSM kk+1 issued before HMMA kk).
// Per-slot TOP-2 -> top-4 per row -> exact fp32 refine.
// ---------------------------------------------------------------------------
__global__ void __launch_bounds__(256, 2)
vq_fused_kernel(const float* __restrict__ cb, const float* __restrict__ x,
                float* __restrict__ out) {
    extern __shared__ char smem[];
    const uint32_t sb = smem_to_u32(smem);
    const int tid  = threadIdx.x;
    const int lane = tid & 31;
    const int warp = tid >> 5;
    const int wm = warp >> 1;          // 0..3 (32 rows each)
    const int wn = warp & 1;           // 0..1 (64 codes each)
    const int r0 = blockIdx.x * MT;

    const int sub  = lane >> 3;
    const int lrow = (sub & 1) * 8 + (lane & 7);
    const int lchk = sub >> 1;

    // ---- loader constants ----
    const int ldr = tid >> 3;          // 0..31
    const int ldc = tid & 7;
    const uint32_t swl = (uint32_t)(ldr * 128 + ((ldc ^ (ldr & 7)) << 4));
    const uint32_t dA[2] = { sb + swl, sb + STAGE_BYTES + swl };
    const uint32_t dB[2] = { sb + 16384 + swl, sb + STAGE_BYTES + 16384 + swl };
    const char* pA = (const char*)g_Ah + ((size_t)(r0 + ldr) * DDIM + ldc * 8) * 2;
    const char* pB = (const char*)g_Ch + ((size_t)ldr * DDIM + ldc * 8) * 2;

    // ---- LDSM base addresses (addr = base ^ (kk<<5)) ----
    uint32_t fullA[2][2], fullB[2][4];
#pragma unroll
    for (int mi = 0; mi < 2; ++mi) {
        int r = wm * 32 + mi * 16 + lrow;
        uint32_t b = (uint32_t)(r * 128 + (((r & 7) ^ lchk) << 4));
        fullA[0][mi] = sb + b;
        fullA[1][mi] = sb + STAGE_BYTES + b;
    }
#pragma unroll
    for (int ni = 0; ni < 4; ++ni) {
        int r = wn * 64 + ni * 16 + lrow;
        uint32_t b = (uint32_t)(r * 128 + (((r & 7) ^ lchk) << 4));
        fullB[0][ni] = sb + 16384 + b;
        fullB[1][ni] = sb + STAGE_BYTES + 16384 + b;
    }

    uint32_t acc[2][8][2];
#pragma unroll
    for (int mi = 0; mi < 2; ++mi)
#pragma unroll
        for (int n8 = 0; n8 < 8; ++n8) { acc[mi][n8][0] = 0u; acc[mi][n8][1] = 0u; }

    // per row-slot TOP-2 (slot = mi*2 + rowhalf)
    float v0[4], v1[4];
    int   i0[4], i1[4];
#pragma unroll
    for (int s = 0; s < 4; ++s) { v0[s] = v1[s] = 3.0e38f; i0[s] = i1[s] = 0x7fffffff; }

    // prologue: tile (chunk 0, kt 0) -> stage 0
#pragma unroll
    for (int i = 0; i < 4; ++i) {
        cp_async16(dA[0] + i * 4096, pA + i * 32768);
        cp_async16(dB[0] + i * 4096, pB + i * 32768);
    }
    CP_COMMIT();

#pragma unroll 1
    for (int chunk = 0; chunk < NCHUNKS; ++chunk) {
#pragma unroll
        for (int kt = 0; kt < 8; ++kt) {
            CP_WAIT(0);
            __syncthreads();

            // issue next tile into the other stage
            if (kt < 7) {
#pragma unroll
                for (int i = 0; i < 4; ++i) {
                    cp_async16(dA[(kt + 1) & 1] + i * 4096,
                               pA + (kt + 1) * 128 + i * 32768);
                    cp_async16(dB[(kt + 1) & 1] + i * 4096,
                               pB + (kt + 1) * 128 + i * 32768);
                }
                CP_COMMIT();
            } else if (chunk < NCHUNKS - 1) {
                const char* pBn = pB + 131072;
#pragma unroll
                for (int i = 0; i < 4; ++i) {
                    cp_async16(dA[0] + i * 4096, pA + i * 32768);
                    cp_async16(dB[0] + i * 4096, pBn + i * 32768);
                }
                CP_COMMIT();
            }

            // compute on stage kt&1 — software-pipelined fragments
            {
                const int s = kt & 1;
                uint32_t a[2][2][4], bf[2][4][4];   // double-buffered frags
                // preload kk=0
#pragma unroll
                for (int mi = 0; mi < 2; ++mi)
                    ldsm_x4(a[0][mi][0], a[0][mi][1], a[0][mi][2], a[0][mi][3],
                            fullA[s][mi]);
#pragma unroll
                for (int ni = 0; ni < 4; ++ni)
                    ldsm_x4(bf[0][ni][0], bf[0][ni][1], bf[0][ni][2], bf[0][ni][3],
                            fullB[s][ni]);
#pragma unroll
                for (int kk = 0; kk < 4; ++kk) {
                    const int cur = kk & 1, nxt = cur ^ 1;
                    if (kk < 3) {   // issue next kk's loads BEFORE this kk's MMAs
#pragma unroll
                        for (int mi = 0; mi < 2; ++mi)
                            ldsm_x4(a[nxt][mi][0], a[nxt][mi][1],
                                    a[nxt][mi][2], a[nxt][mi][3],
                                    fullA[s][mi] ^ (uint32_t)((kk + 1) << 5));
#pragma unroll
                        for (int ni = 0; ni < 4; ++ni)
                            ldsm_x4(bf[nxt][ni][0], bf[nxt][ni][1],
                                    bf[nxt][ni][2], bf[nxt][ni][3],
                                    fullB[s][ni] ^ (uint32_t)((kk + 1) << 5));
                    }
#pragma unroll
                    for (int mi = 0; mi < 2; ++mi)
#pragma unroll
                        for (int n8 = 0; n8 < 8; ++n8)
                            mma16816_f16(acc[mi][n8], a[cur][mi],
                                         bf[cur][n8 >> 1][n8 & 1],
                                         bf[cur][n8 >> 1][(n8 & 1) + 2]);
                }
            }

            // chunk epilogue: TOP-2 per slot
            if (kt == 7) {
                const int c0 = chunk * NT;
#pragma unroll
                for (int n8 = 0; n8 < 8; ++n8) {
                    const int col = c0 + wn * 64 + n8 * 8 + 2 * (lane & 3);
                    const float cn0 = __ldg(&g_cnorm[col]);
                    const float cn1 = __ldg(&g_cnorm[col + 1]);
#pragma unroll
                    for (int mi = 0; mi < 2; ++mi) {
#pragma unroll
                        for (int r = 0; r < 2; ++r) {
                            const int slot = mi * 2 + r;
                            float2 f = __half22float2(
                                *reinterpret_cast<__half2*>(&acc[mi][n8][r]));
                            float d0 = fmaf(-2.f, f.x, cn0);
                            float d1 = fmaf(-2.f, f.y, cn1);
                            if (d0 < v1[slot]) {
                                if (d0 < v0[slot]) {
                                    v1[slot] = v0[slot]; i1[slot] = i0[slot];
                                    v0[slot] = d0;       i0[slot] = col;
                                } else { v1[slot] = d0; i1[slot] = col; }
                            }
                            if (d1 < v1[slot]) {
                                if (d1 < v0[slot]) {
                                    v1[slot] = v0[slot]; i1[slot] = i0[slot];
                                    v0[slot] = d1;       i0[slot] = col + 1;
                                } else { v1[slot] = d1; i1[slot] = col + 1; }
                            }
                            acc[mi][n8][r] = 0u;
                        }
                    }
                }
            }
        }
        pB += 131072;   // next 128 codebook rows
    }

    // ---- Merge 8 threads x 2 entries per row -> top-4 per row (in smem) ----
    __syncthreads();
    float* mv   = reinterpret_cast<float*>(smem);            // [128][16]
    int*   md   = reinterpret_cast<int*>(smem + 8192);       // [128][16]
    int*   cand = reinterpret_cast<int*>(smem + 16384);      // [128][4]
#pragma unroll
    for (int slot = 0; slot < 4; ++slot) {
        const int mi = slot >> 1, rh = slot & 1;
        const int row = wm * 32 + mi * 16 + rh * 8 + (lane >> 2);
        const int col = wn * 8 + (lane & 3) * 2;
        mv[row * 16 + col]     = v0[slot];
        md[row * 16 + col]     = i0[slot];
        mv[row * 16 + col + 1] = v1[slot];
        md[row * 16 + col + 1] = i1[slot];
    }
    __syncthreads();
    if (tid < MT) {
        float tv[4] = {3.0e38f, 3.0e38f, 3.0e38f, 3.0e38f};
        int   ti[4] = {0x7fffffff, 0x7fffffff, 0x7fffffff, 0x7fffffff};
#pragma unroll 4
        for (int e = 0; e < 16; ++e) {
            float v = mv[tid * 16 + e];
            int   d = md[tid * 16 + e];
            if (v < tv[3] || (v == tv[3] && d < ti[3])) {
                tv[3] = v; ti[3] = d;
#pragma unroll
                for (int j = 3; j >= 1; --j) {
                    if (tv[j] < tv[j-1] || (tv[j] == tv[j-1] && ti[j] < ti[j-1])) {
                        float fv = tv[j]; tv[j] = tv[j-1]; tv[j-1] = fv;
                        int   fi = ti[j]; ti[j] = ti[j-1]; ti[j-1] = fi;
                    }
                }
            }
        }
#pragma unroll
        for (int j = 0; j < 4; ++j) cand[tid * 4 + j] = ti[j];
    }
    __syncthreads();

    // ---- Fused exact refine + gather: warp w refines rows [w*16, w*16+16) ----
#pragma unroll 1
    for (int rr = 0; rr < 16; ++rr) {
        const int row = warp * 16 + rr;
        const int n = r0 + row;

        float xr[16];
#pragma unroll
        for (int j = 0; j < 16; ++j) xr[j] = x[(size_t)n * DDIM + j * 32 + lane];

        float bv = 3.0e38f;
        int   bi = 0x7fffffff;
#pragma unroll
        for (int c = 0; c < NCAND; ++c) {
            const int k = cand[row * 4 + c];
            const float* crow = cb + (size_t)k * DDIM;
            float s = 0.f;
#pragma unroll
            for (int j = 0; j < 16; ++j) s = fmaf(xr[j], __ldg(crow + j * 32 + lane), s);
#pragma unroll
            for (int o = 16; o > 0; o >>= 1) s += __shfl_xor_sync(0xffffffffu, s, o);
            float d2 = fmaf(-2.f, s, __ldg(&g_cnorm[k]));
            if (d2 < bv || (d2 == bv && k < bi)) { bv = d2; bi = k; }
        }

        const float* q = cb + (size_t)bi * DDIM;
#pragma unroll
        for (int j = 0; j < 16; ++j) {
            float qv = __ldg(q + j * 32 + lane);
            float xv = xr[j];
            out[(size_t)n * DDIM + j * 32 + lane] = (qv - xv) + xv;
        }
    }
}

// ---------------------------------------------------------------------------
extern "C" void kernel_launch(void* const* d_in, const int* in_sizes, int n_in,
                              void* d_out, int out_size) {
    const float* inputs   = (const float*)d_in[0];
    const float* codebook = (const float*)d_in[1];
    float* out = (float*)d_out;

    cudaFuncSetAttribute(vq_fused_kernel, cudaFuncAttributeMaxDynamicSharedMemorySize,
                         SMEM_TOTAL);

    prep_kernel<<<KCODES + N_ROWS, 128>>>(inputs, codebook);
    vq_fused_kernel<<<N_ROWS / MT, 256, SMEM_TOTAL>>>(codebook, inputs, out);
}

// round 15
// speedup vs baseline: 2.5735x; 1.0046x over previous
#include <cuda_runtime.h>
#include <cuda_fp16.h>
#include <cstdint>

// Problem constants
#define N_ROWS 32768
#define DDIM   512
#define KCODES 4096

// Coarse tiling (fp16 HMMA, f16 accumulate)
#define MT 128                 // rows per CTA
#define NT 128                 // codes per chunk
#define BK 64                  // K fp16 per SMEM tile (128B rows)
#define NCHUNKS (KCODES / NT)          // 32
#define STAGE_BYTES 32768      // A 16KB + B 16KB
#define SMEM_TOTAL (2 * STAGE_BYTES)   // 65536

#define NCAND 4

// ---------------- scratch ----------------
__device__ __half g_Ah[(size_t)N_ROWS * DDIM];
__device__ __half g_Ch[(size_t)KCODES * DDIM];
__device__ float g_cnorm[KCODES];

// ---------------- PTX helpers ----------------
__device__ __forceinline__ uint32_t smem_to_u32(const void* p) {
    uint32_t a;
    asm("{ .reg .u64 t; cvta.to.shared.u64 t, %1; cvt.u32.u64 %0, t; }" : "=r"(a) : "l"(p));
    return a;
}
__device__ __forceinline__ void cp_async16(uint32_t dst, const void* src) {
    asm volatile("cp.async.cg.shared.global [%0], [%1], 16;" :: "r"(dst), "l"(src) : "memory");
}
#define CP_COMMIT() asm volatile("cp.async.commit_group;" ::: "memory")
#define CP_WAIT(n)  asm volatile("cp.async.wait_group %0;" :: "n"(n) : "memory")

__device__ __forceinline__ void ldsm_x4(uint32_t& r0, uint32_t& r1, uint32_t& r2,
                                        uint32_t& r3, uint32_t addr) {
    asm volatile("ldmatrix.sync.aligned.m8n8.x4.shared.b16 {%0,%1,%2,%3}, [%4];"
                 : "=r"(r0), "=r"(r1), "=r"(r2), "=r"(r3) : "r"(addr));
}
// fp16 x fp16 -> fp16 accumulate
__device__ __forceinline__ void mma16816_f16(uint32_t* d, const uint32_t* a,
                                             uint32_t b0, uint32_t b1) {
    asm volatile(
        "mma.sync.aligned.m16n8k16.row.col.f16.f16.f16.f16 "
        "{%0,%1}, {%2,%3,%4,%5}, {%6,%7}, {%0,%1};"
        : "+r"(d[0]), "+r"(d[1])
        : "r"(a[0]), "r"(a[1]), "r"(a[2]), "r"(a[3]), "r"(b0), "r"(b1));
}

// ---------------------------------------------------------------------------
// Prep: codebook only — fp16 convert + exact fp32 ||c||^2. 4096 blocks.
// ---------------------------------------------------------------------------
__global__ void prep_codebook_kernel(const float* __restrict__ cb) {
    const int k = blockIdx.x;
    float4 v = reinterpret_cast<const float4*>(cb + (size_t)k * DDIM)[threadIdx.x];
    __half h[4] = {__float2half_rn(v.x), __float2half_rn(v.y),
                   __float2half_rn(v.z), __float2half_rn(v.w)};
    reinterpret_cast<uint2*>(g_Ch)[k * (DDIM / 4) + threadIdx.x] =
        *reinterpret_cast<uint2*>(h);
    float s = v.x * v.x + v.y * v.y + v.z * v.z + v.w * v.w;
#pragma unroll
    for (int o = 16; o > 0; o >>= 1) s += __shfl_xor_sync(0xffffffffu, s, o);
    __shared__ float ws[4];
    if ((threadIdx.x & 31) == 0) ws[threadIdx.x >> 5] = s;
    __syncthreads();
    if (threadIdx.x == 0) g_cnorm[k] = ws[0] + ws[1] + ws[2] + ws[3];
}

// ---------------------------------------------------------------------------
// Fused: per-CTA A conversion + coarse GEMM + exact refine.
// Grid 256 CTAs x 256 threads, 2 CTAs/SM. 8 warps (4m x 2n), warp tile 32x64.
// ---------------------------------------------------------------------------
__global__ void __launch_bounds__(256, 2)
vq_fused_kernel(const float* __restrict__ cb, const float* __restrict__ x,
                float* __restrict__ out) {
    extern __shared__ char smem[];
    const uint32_t sb = smem_to_u32(smem);
    const int tid  = threadIdx.x;
    const int lane = tid & 31;
    const int warp = tid >> 5;
    const int wm = warp >> 1;          // 0..3 (32 rows each)
    const int wn = warp & 1;           // 0..1 (64 codes each)
    const int r0 = blockIdx.x * MT;

    const int sub  = lane >> 3;
    const int lrow = (sub & 1) * 8 + (lane & 7);
    const int lchk = sub >> 1;

    // ---- loader constants ----
    const int ldr = tid >> 3;          // 0..31
    const int ldc = tid & 7;
    const uint32_t swl = (uint32_t)(ldr * 128 + ((ldc ^ (ldr & 7)) << 4));
    const uint32_t dA[2] = { sb + swl, sb + STAGE_BYTES + swl };
    const uint32_t dB[2] = { sb + 16384 + swl, sb + STAGE_BYTES + 16384 + swl };
    const char* pA = (const char*)g_Ah + ((size_t)(r0 + ldr) * DDIM + ldc * 8) * 2;
    const char* pB = (const char*)g_Ch + ((size_t)ldr * DDIM + ldc * 8) * 2;

    // ---- LDSM base addresses (addr = base ^ (kk<<5)) ----
    uint32_t fullA[2][2], fullB[2][4];
#pragma unroll
    for (int mi = 0; mi < 2; ++mi) {
        int r = wm * 32 + mi * 16 + lrow;
        uint32_t b = (uint32_t)(r * 128 + (((r & 7) ^ lchk) << 4));
        fullA[0][mi] = sb + b;
        fullA[1][mi] = sb + STAGE_BYTES + b;
    }
#pragma unroll
    for (int ni = 0; ni < 4; ++ni) {
        int r = wn * 64 + ni * 16 + lrow;
        uint32_t b = (uint32_t)(r * 128 + (((r & 7) ^ lchk) << 4));
        fullB[0][ni] = sb + 16384 + b;
        fullB[1][ni] = sb + STAGE_BYTES + 16384 + b;
    }

    // ---- prologue part 1: B tile 0 load (independent of A conversion) ----
#pragma unroll
    for (int i = 0; i < 4; ++i)
        cp_async16(dB[0] + i * 4096, pB + i * 32768);
    CP_COMMIT();

    // ---- convert this CTA's 128 input rows fp32 -> fp16 into g_Ah slice ----
    // 128 rows x 128 float4 = 16384 float4; 256 threads x 64 iters.
    {
        const float4* xs = reinterpret_cast<const float4*>(x + (size_t)r0 * DDIM);
        uint2* ad = reinterpret_cast<uint2*>(g_Ah + (size_t)r0 * DDIM);
#pragma unroll 4
        for (int i = 0; i < 64; ++i) {
            int idx = tid + i * 256;
            float4 v = xs[idx];
            __half h[4] = {__float2half_rn(v.x), __float2half_rn(v.y),
                           __float2half_rn(v.z), __float2half_rn(v.w)};
            ad[idx] = *reinterpret_cast<uint2*>(h);
        }
    }
    __threadfence_block();
    __syncthreads();

    // ---- prologue part 2: A tile 0 ----
#pragma unroll
    for (int i = 0; i < 4; ++i)
        cp_async16(dA[0] + i * 4096, pA + i * 32768);
    CP_COMMIT();

    uint32_t acc[2][8][2];
#pragma unroll
    for (int mi = 0; mi < 2; ++mi)
#pragma unroll
        for (int n8 = 0; n8 < 8; ++n8) { acc[mi][n8][0] = 0u; acc[mi][n8][1] = 0u; }

    // per row-slot TOP-2 (slot = mi*2 + rowhalf)
    float v0[4], v1[4];
    int   i0[4], i1[4];
#pragma unroll
    for (int s = 0; s < 4; ++s) { v0[s] = v1[s] = 3.0e38f; i0[s] = i1[s] = 0x7fffffff; }

#pragma unroll 1
    for (int chunk = 0; chunk < NCHUNKS; ++chunk) {
#pragma unroll
        for (int kt = 0; kt < 8; ++kt) {
            CP_WAIT(0);
            __syncthreads();

            // issue next tile into the other stage
            if (kt < 7) {
#pragma unroll
                for (int i = 0; i < 4; ++i) {
                    cp_async16(dA[(kt + 1) & 1] + i * 4096,
                               pA + (kt + 1) * 128 + i * 32768);
                    cp_async16(dB[(kt + 1) & 1] + i * 4096,
                               pB + (kt + 1) * 128 + i * 32768);
                }
                CP_COMMIT();
            } else if (chunk < NCHUNKS - 1) {
                const char* pBn = pB + 131072;
#pragma unroll
                for (int i = 0; i < 4; ++i) {
                    cp_async16(dA[0] + i * 4096, pA + i * 32768);
                    cp_async16(dB[0] + i * 4096, pBn + i * 32768);
                }
                CP_COMMIT();
            }

            // compute on stage kt&1
            {
                const int s = kt & 1;
#pragma unroll
                for (int kk = 0; kk < 4; ++kk) {
                    uint32_t a[2][4];
#pragma unroll
                    for (int mi = 0; mi < 2; ++mi)
                        ldsm_x4(a[mi][0], a[mi][1], a[mi][2], a[mi][3],
                                fullA[s][mi] ^ (uint32_t)(kk << 5));
                    uint32_t bf[4][4];
#pragma unroll
                    for (int ni = 0; ni < 4; ++ni)
                        ldsm_x4(bf[ni][0], bf[ni][1], bf[ni][2], bf[ni][3],
                                fullB[s][ni] ^ (uint32_t)(kk << 5));
#pragma unroll
                    for (int mi = 0; mi < 2; ++mi)
#pragma unroll
                        for (int n8 = 0; n8 < 8; ++n8)
                            mma16816_f16(acc[mi][n8], a[mi],
                                         bf[n8 >> 1][n8 & 1], bf[n8 >> 1][(n8 & 1) + 2]);
                }
            }

            // chunk epilogue: TOP-2 per slot
            if (kt == 7) {
                const int c0 = chunk * NT;
#pragma unroll
                for (int n8 = 0; n8 < 8; ++n8) {
                    const int col = c0 + wn * 64 + n8 * 8 + 2 * (lane & 3);
                    const float cn0 = __ldg(&g_cnorm[col]);
                    const float cn1 = __ldg(&g_cnorm[col + 1]);
#pragma unroll
                    for (int mi = 0; mi < 2; ++mi) {
#pragma unroll
                        for (int r = 0; r < 2; ++r) {
                            const int slot = mi * 2 + r;
                            float2 f = __half22float2(
                                *reinterpret_cast<__half2*>(&acc[mi][n8][r]));
                            float d0 = fmaf(-2.f, f.x, cn0);
                            float d1 = fmaf(-2.f, f.y, cn1);
                            if (d0 < v1[slot]) {
                                if (d0 < v0[slot]) {
                                    v1[slot] = v0[slot]; i1[slot] = i0[slot];
                                    v0[slot] = d0;       i0[slot] = col;
                                } else { v1[slot] = d0; i1[slot] = col; }
                            }
                            if (d1 < v1[slot]) {
                                if (d1 < v0[slot]) {
                                    v1[slot] = v0[slot]; i1[slot] = i0[slot];
                                    v0[slot] = d1;       i0[slot] = col + 1;
                                } else { v1[slot] = d1; i1[slot] = col + 1; }
                            }
                            acc[mi][n8][r] = 0u;
                        }
                    }
                }
            }
        }
        pB += 131072;   // next 128 codebook rows
    }

    // ---- Merge 8 threads x 2 entries per row -> top-4 per row (in smem) ----
    __syncthreads();
    float* mv   = reinterpret_cast<float*>(smem);            // [128][16]
    int*   md   = reinterpret_cast<int*>(smem + 8192);       // [128][16]
    int*   cand = reinterpret_cast<int*>(smem + 16384);      // [128][4]
#pragma unroll
    for (int slot = 0; slot < 4; ++slot) {
        const int mi = slot >> 1, rh = slot & 1;
        const int row = wm * 32 + mi * 16 + rh * 8 + (lane >> 2);
        const int col = wn * 8 + (lane & 3) * 2;
        mv[row * 16 + col]     = v0[slot];
        md[row * 16 + col]     = i0[slot];
        mv[row * 16 + col + 1] = v1[slot];
        md[row * 16 + col + 1] = i1[slot];
    }
    __syncthreads();
    if (tid < MT) {
        float tv[4] = {3.0e38f, 3.0e38f, 3.0e38f, 3.0e38f};
        int   ti[4] = {0x7fffffff, 0x7fffffff, 0x7fffffff, 0x7fffffff};
#pragma unroll 4
        for (int e = 0; e < 16; ++e) {
            float v = mv[tid * 16 + e];
            int   d = md[tid * 16 + e];
            if (v < tv[3] || (v == tv[3] && d < ti[3])) {
                tv[3] = v; ti[3] = d;
#pragma unroll
                for (int j = 3; j >= 1; --j) {
                    if (tv[j] < tv[j-1] || (tv[j] == tv[j-1] && ti[j] < ti[j-1])) {
                        float fv = tv[j]; tv[j] = tv[j-1]; tv[j-1] = fv;
                        int   fi = ti[j]; ti[j] = ti[j-1]; ti[j-1] = fi;
                    }
                }
            }
        }
#pragma unroll
        for (int j = 0; j < 4; ++j) cand[tid * 4 + j] = ti[j];
    }
    __syncthreads();

    // ---- Fused exact refine + gather: warp w refines rows [w*16, w*16+16) ----
#pragma unroll 1
    for (int rr = 0; rr < 16; ++rr) {
        const int row = warp * 16 + rr;
        const int n = r0 + row;

        float xr[16];
#pragma unroll
        for (int j = 0; j < 16; ++j) xr[j] = x[(size_t)n * DDIM + j * 32 + lane];

        float bv = 3.0e38f;
        int   bi = 0x7fffffff;
#pragma unroll
        for (int c = 0; c < NCAND; ++c) {
            const int k = cand[row * 4 + c];
            const float* crow = cb + (size_t)k * DDIM;
            float s = 0.f;
#pragma unroll
            for (int j = 0; j < 16; ++j) s = fmaf(xr[j], __ldg(crow + j * 32 + lane), s);
#pragma unroll
            for (int o = 16; o > 0; o >>= 1) s += __shfl_xor_sync(0xffffffffu, s, o);
            float d2 = fmaf(-2.f, s, __ldg(&g_cnorm[k]));
            if (d2 < bv || (d2 == bv && k < bi)) { bv = d2; bi = k; }
        }

        const float* q = cb + (size_t)bi * DDIM;
#pragma unroll
        for (int j = 0; j < 16; ++j) {
            float qv = __ldg(q + j * 32 + lane);
            float xv = xr[j];
            out[(size_t)n * DDIM + j * 32 + lane] = (qv - xv) + xv;
        }
    }
}

// ---------------------------------------------------------------------------
extern "C" void kernel_launch(void* const* d_in, const int* in_sizes, int n_in,
                              void* d_out, int out_size) {
    const float* inputs   = (const float*)d_in[0];
    const float* codebook = (const float*)d_in[1];
    float* out = (float*)d_out;

    cudaFuncSetAttribute(vq_fused_kernel, cudaFuncAttributeMaxDynamicSharedMemorySize,
                         SMEM_TOTAL);

    prep_codebook_kernel<<<KCODES, 128>>>(codebook);
    vq_fused_kernel<<<N_ROWS / MT, 256, SMEM_TOTAL>>>(codebook, inputs, out);
}